// round 12
// baseline (speedup 1.0000x reference)
#include <cuda_runtime.h>
#include <cuda_bf16.h>
#include <math.h>
#include <stdint.h>

// ---------------------------------------------------------------------------
// DirectRegressionHead: 2-layer GRU encoder (7 steps) + 12-step GRU decoder.
// B=32768, H=256, CTX=128, PRED=12.
// bf16x3 split-precision mma.sync.m16n8k16, fp32 accumulate.
// Cell kernel: warp-specialized producer/consumer pipeline (320 thr:
// 8 mma warps + 2 staging warps, double-buffered A and W, named barriers).
// Proj kernel: unchanged R10 engine.
// ---------------------------------------------------------------------------

#define BMAX 32768
#define HDIM 256
#define CTXD 128
#define PRED 12
#define STR 72            // smem tile k-stride in bf16 (64 + 8 pad)
#define WHALF (96 * STR)  // elements between W hi and lo planes in one buffer

// packed weight layout (bf16 elements, hi plane; lo plane at +WTOT)
#define O_WHH0 0L
#define O_WIH1 196608L
#define O_WHH1 393216L
#define O_WHHS 589824L
#define O_WCTX 786432L
#define O_PA   884736L
#define WTOT   933888L

// ---- cell kernel smem (bytes) ----
// A0 0 | A1 36864 | W0 73728 | W1 101376 | wd_s 129024 | total 132096
// gbuf (73728B) aliases A0+A1.
#define A0_OFF 0
#define A1_OFF 36864
#define W0_OFF 73728
#define W1_OFF 101376
#define WD_OFF 129024
#define GRU_SMEM 132096
#define T_ALL 320
#define NPROD 64
#define B_FULL0 1
#define B_EMPTY0 3

// ---- proj kernel smem (R10 layout) ----
#define OFF_ALO 18432
#define OFF_WB0 36864
#define OFF_WB1 64512
#define OFF_EXT 92160
#define PROJ_SMEM 192512

// --- static device scratch ---
__device__ float g_h0a[BMAX * HDIM];
__device__ float g_h0b[BMAX * HDIM];
__device__ float g_h1a[BMAX * HDIM];
__device__ float g_h1b[BMAX * HDIM];
__device__ float g_obsin[8 * BMAX * 6];
__device__ float g_ctxp[BMAX * CTXD];
__device__ float g_dynA[BMAX * 6];
__device__ float g_dynB[BMAX * 6];
__device__ float g_gictx[(size_t)BMAX * 768];
__device__ float g_wdyn0[768 * 8];
__device__ float g_wdynS[768 * 8];
__device__ __nv_bfloat16 g_wpack[2 * WTOT];

// ---------------- async-copy / barrier helpers ----------------
__device__ __forceinline__ void cp16(void* dst, const void* src) {
    uint32_t d = (uint32_t)__cvta_generic_to_shared(dst);
    asm volatile("cp.async.cg.shared.global [%0], [%1], 16;" :: "r"(d), "l"(src));
}
__device__ __forceinline__ void cp_commit() { asm volatile("cp.async.commit_group;"); }
__device__ __forceinline__ void cp_wait0() { asm volatile("cp.async.wait_group 0;"); }
__device__ __forceinline__ void cp_wait1() { asm volatile("cp.async.wait_group 1;"); }
__device__ __forceinline__ void bar_sync(int id, int cnt) {
    asm volatile("bar.sync %0, %1;" :: "r"(id), "r"(cnt) : "memory");
}
__device__ __forceinline__ void bar_arrive(int id, int cnt) {
    asm volatile("bar.arrive %0, %1;" :: "r"(id), "r"(cnt) : "memory");
}

// ---------------------------------------------------------------------------
__global__ void zero_kernel(float* __restrict__ p, int n) {
    int stride = gridDim.x * blockDim.x;
    for (int i = blockIdx.x * blockDim.x + threadIdx.x; i * 4 < n; i += stride)
        ((float4*)p)[i] = make_float4(0.f, 0.f, 0.f, 0.f);
}

__global__ void pack_kernel(const float* __restrict__ W, int rows, int ld, int koff,
                            int K, int Kpad, long dst, __nv_bfloat16* __restrict__ wp) {
    int i = blockIdx.x * blockDim.x + threadIdx.x;
    if (i >= rows * Kpad) return;
    int r = i / Kpad, k = i - r * Kpad;
    float v = (k < K) ? W[(size_t)r * ld + koff + k] : 0.f;
    __nv_bfloat16 h = __float2bfloat16(v);
    wp[dst + i] = h;
    wp[WTOT + dst + i] = __float2bfloat16(v - __bfloat162float(h));
}

__global__ void wdyn_pack_kernel(const float* __restrict__ src, int ld, int koff,
                                 float* __restrict__ dst) {
    int i = blockIdx.x * blockDim.x + threadIdx.x;
    if (i >= 768 * 8) return;
    int r = i >> 3, q = i & 7;
    dst[i] = (q < 6) ? src[(size_t)r * ld + koff + q] : 0.f;
}

// ---------------------------------------------------------------------------
__global__ void prep_kernel(const float* __restrict__ traj,
                            const float* __restrict__ me,
                            float* __restrict__ obsin,
                            float* __restrict__ dyn, int B, int T) {
    int b = blockIdx.x * blockDim.x + threadIdx.x;
    if (b >= B) return;
    float vx[8], vy[8], mx[8], my_[8];
    int TS = T - 1;
    if (TS > 8) TS = 8;
    for (int t = 0; t < TS; t++) {
        vx[t]  = traj[((size_t)(t + 1) * B + b) * 2 + 0] - traj[((size_t)t * B + b) * 2 + 0];
        vy[t]  = traj[((size_t)(t + 1) * B + b) * 2 + 1] - traj[((size_t)t * B + b) * 2 + 1];
        mx[t]  = me[((size_t)(t + 1) * B + b) * 2 + 0] - me[((size_t)t * B + b) * 2 + 0];
        my_[t] = me[((size_t)(t + 1) * B + b) * 2 + 1] - me[((size_t)t * B + b) * 2 + 1];
    }
    for (int t = 0; t < TS; t++) {
        int ta = (t == 0) ? 1 : t;
        float ax = vx[ta] - vx[ta - 1];
        float ay = vy[ta] - vy[ta - 1];
        float* o = obsin + ((size_t)t * B + b) * 6;
        o[0] = vx[t]; o[1] = vy[t];
        o[2] = mx[t]; o[3] = my_[t];
        o[4] = ax;    o[5] = ay;
    }
    dyn[(size_t)b * 6 + 0] = vx[TS - 1];
    dyn[(size_t)b * 6 + 1] = vy[TS - 1];
    dyn[(size_t)b * 6 + 2] = vx[TS - 1] - vx[TS - 2];
    dyn[(size_t)b * 6 + 3] = vy[TS - 1] - vy[TS - 2];
    dyn[(size_t)b * 6 + 4] = mx[TS - 1];
    dyn[(size_t)b * 6 + 5] = my_[TS - 1];
}

// ---------------------------------------------------------------------------
__global__ __launch_bounds__(256) void ctx_kernel(const float* __restrict__ ctx,
                                                  const float* __restrict__ Cw,
                                                  const float* __restrict__ cb,
                                                  float* __restrict__ outp, int B) {
    __shared__ float Cs[64][128];
    __shared__ float Wc[16][128];
    int tid = threadIdx.x;
    int m0 = blockIdx.x * 64;
    for (int i = tid; i < 64 * 128 / 4; i += 256) {
        int m = m0 + (i * 4) / 128;
        float4 v = make_float4(0.f, 0.f, 0.f, 0.f);
        if (m < B) v = *(const float4*)&ctx[(size_t)m0 * 128 + i * 4];
        ((float4*)Cs)[i] = v;
    }
    __syncthreads();
    int w = tid >> 5, lane = tid & 31;
    float acc[8][4];
#pragma unroll
    for (int i = 0; i < 8; i++)
#pragma unroll
        for (int u = 0; u < 4; u++) acc[i][u] = 0.f;

    for (int k0 = 0; k0 < 128; k0 += 16) {
        for (int i = tid; i < 16 * 128; i += 256) {
            int kk = i & 15, u = i >> 4;
            Wc[kk][u] = Cw[(size_t)u * 128 + k0 + kk];
        }
        __syncthreads();
#pragma unroll
        for (int kk = 0; kk < 16; kk++) {
            float wv[4];
#pragma unroll
            for (int u = 0; u < 4; u++) wv[u] = Wc[kk][lane * 4 + u];
#pragma unroll
            for (int i = 0; i < 8; i++) {
                float a = Cs[w * 8 + i][k0 + kk];
#pragma unroll
                for (int u = 0; u < 4; u++) acc[i][u] += a * wv[u];
            }
        }
        __syncthreads();
    }
#pragma unroll
    for (int i = 0; i < 8; i++) {
        int m = m0 + w * 8 + i;
        if (m >= B) continue;
#pragma unroll
        for (int u = 0; u < 4; u++) {
            int ug = lane * 4 + u;
            outp[(size_t)m * 128 + ug] = acc[i][u] + cb[ug];
        }
    }
}

// ---------------------------------------------------------------------------
// tensor-core helpers
// ---------------------------------------------------------------------------
__device__ __forceinline__ void mma_bf16(float* c, const uint32_t* a, uint32_t b0, uint32_t b1) {
    asm volatile(
        "mma.sync.aligned.m16n8k16.row.col.f32.bf16.bf16.f32 "
        "{%0,%1,%2,%3}, {%4,%5,%6,%7}, {%8,%9}, {%0,%1,%2,%3};\n"
        : "+f"(c[0]), "+f"(c[1]), "+f"(c[2]), "+f"(c[3])
        : "r"(a[0]), "r"(a[1]), "r"(a[2]), "r"(a[3]), "r"(b0), "r"(b1));
}

__device__ __forceinline__ void ldsm_x4(uint32_t* r, const __nv_bfloat16* base,
                                        int row, int col, int lane) {
    int g = lane >> 3, rr = lane & 7;
    const __nv_bfloat16* p = base + (size_t)(row + (g & 1) * 8 + rr) * STR + col + (g >> 1) * 8;
    uint32_t addr = (uint32_t)__cvta_generic_to_shared(p);
    asm volatile("ldmatrix.sync.aligned.m8n8.x4.shared.b16 {%0,%1,%2,%3}, [%4];"
                 : "=r"(r[0]), "=r"(r[1]), "=r"(r[2]), "=r"(r[3]) : "r"(addr));
}

__device__ __forceinline__ void ldsm_x2(uint32_t* r, const __nv_bfloat16* base,
                                        int row, int col, int lane) {
    int l = lane & 15;
    int g = l >> 3, rr = l & 7;
    const __nv_bfloat16* p = base + (size_t)(row + rr) * STR + col + g * 8;
    uint32_t addr = (uint32_t)__cvta_generic_to_shared(p);
    asm volatile("ldmatrix.sync.aligned.m8n8.x2.shared.b16 {%0,%1}, [%2];"
                 : "=r"(r[0]), "=r"(r[1]) : "r"(addr));
}

template<bool ALT>
__device__ __forceinline__ void mma_all(float (&accA)[2][6][4], float (&accH)[2][2][4],
                                        uint32_t a[2][4], uint32_t b[6][2]) {
#pragma unroll
    for (int mf = 0; mf < 2; mf++)
#pragma unroll
        for (int f = 0; f < 6; f++) {
            float* c = (ALT && f >= 4) ? accH[mf][f - 4] : accA[mf][f];
            mma_bf16(c, a[mf], b[f][0], b[f][1]);
        }
}

// consumer: one staged chunk (A: Ahi/Alo at Ab, W: Whi/Wlo at Wb), 3 passes
template<bool ALT>
__device__ __forceinline__ void tile_mma4(char* Ab, char* Wb,
                                          float (&accA)[2][6][4], float (&accH)[2][2][4],
                                          int mw, int nw, int lane) {
    __nv_bfloat16* Ahi = (__nv_bfloat16*)Ab;
    __nv_bfloat16* Alo = (__nv_bfloat16*)(Ab + 18432);
    __nv_bfloat16* Whi = (__nv_bfloat16*)Wb;
    __nv_bfloat16* Wlo = Whi + WHALF;
#pragma unroll
    for (int ks = 0; ks < 4; ks++) {
        uint32_t ah[2][4], al[2][4], b[6][2];
        ldsm_x4(ah[0], Ahi, mw * 32,      ks * 16, lane);
        ldsm_x4(ah[1], Ahi, mw * 32 + 16, ks * 16, lane);
        ldsm_x4(al[0], Alo, mw * 32,      ks * 16, lane);
        ldsm_x4(al[1], Alo, mw * 32 + 16, ks * 16, lane);
#pragma unroll
        for (int f = 0; f < 6; f++) ldsm_x2(b[f], Whi, (f * 2 + nw) * 8, ks * 16, lane);
        mma_all<ALT>(accA, accH, ah, b);   // hi*hi
        mma_all<ALT>(accA, accH, al, b);   // lo*hi
#pragma unroll
        for (int f = 0; f < 6; f++) ldsm_x2(b[f], Wlo, (f * 2 + nw) * 8, ks * 16, lane);
        mma_all<ALT>(accA, accH, ah, b);   // hi*lo
    }
}

// ---------------------------------------------------------------------------
// R10 gemm_phase (used by proj kernel only; 256 threads, self-staging)
// ---------------------------------------------------------------------------
template<bool ALT>
__device__ __forceinline__ void gemm_phase(
    const float* __restrict__ X, int ldx, int K,
    const __nv_bfloat16* __restrict__ wHi, const __nv_bfloat16* __restrict__ wLo,
    int ldwp, int plane_stride,
    int m0, int n0, int B,
    __nv_bfloat16* Ahi, __nv_bfloat16* Alo, __nv_bfloat16* Wb0, __nv_bfloat16* Wb1,
    float (&accA)[2][6][4], float (&accH)[2][2][4]) {
    const int tid = threadIdx.x;
    const int lane = tid & 31;
    const int w = tid >> 5;
    const int mw = w >> 1;
    const int nw = w & 1;
    const int nch = K / 64;

    for (int i = tid; i < 768; i += 256) {
        int r = i >> 3, q = i & 7;
        int grow = (r >> 5) * plane_stride + n0 + (r & 31);
        size_t so = (size_t)grow * ldwp + q * 8;
        cp16(Wb0 + (size_t)r * STR + q * 8, wHi + so);
        cp16(Wb0 + WHALF + (size_t)r * STR + q * 8, wLo + so);
    }
    cp_commit();

    for (int c = 0; c < nch; c++) {
        int k0 = c * 64;
        __syncthreads();
        for (int i = tid; i < 2048; i += 256) {
            int r = i >> 4, cc = (i & 15) * 4;
            int m = m0 + r;
            float4 v = make_float4(0.f, 0.f, 0.f, 0.f);
            if (m < B) v = *(const float4*)(X + (size_t)m * ldx + k0 + cc);
            __nv_bfloat162 h0 = __floats2bfloat162_rn(v.x, v.y);
            __nv_bfloat162 h1 = __floats2bfloat162_rn(v.z, v.w);
            *(__nv_bfloat162*)(Ahi + (size_t)r * STR + cc)     = h0;
            *(__nv_bfloat162*)(Ahi + (size_t)r * STR + cc + 2) = h1;
            __nv_bfloat162 l0 = __floats2bfloat162_rn(v.x - __bfloat162float(h0.x),
                                                      v.y - __bfloat162float(h0.y));
            __nv_bfloat162 l1 = __floats2bfloat162_rn(v.z - __bfloat162float(h1.x),
                                                      v.w - __bfloat162float(h1.y));
            *(__nv_bfloat162*)(Alo + (size_t)r * STR + cc)     = l0;
            *(__nv_bfloat162*)(Alo + (size_t)r * STR + cc + 2) = l1;
        }
        if (c + 1 < nch) {
            __nv_bfloat16* Wd = (c & 1) ? Wb0 : Wb1;
            int k1 = (c + 1) * 64;
            for (int i = tid; i < 768; i += 256) {
                int r = i >> 3, q = i & 7;
                int grow = (r >> 5) * plane_stride + n0 + (r & 31);
                size_t so = (size_t)grow * ldwp + k1 + q * 8;
                cp16(Wd + (size_t)r * STR + q * 8, wHi + so);
                cp16(Wd + WHALF + (size_t)r * STR + q * 8, wLo + so);
            }
            cp_commit();
            cp_wait1();
        } else {
            cp_wait0();
        }
        __syncthreads();
        const __nv_bfloat16* Whi = (c & 1) ? Wb1 : Wb0;
        const __nv_bfloat16* Wlo2 = Whi + WHALF;
#pragma unroll
        for (int ks = 0; ks < 4; ks++) {
            uint32_t ah[2][4], al[2][4], b[6][2];
            ldsm_x4(ah[0], Ahi, mw * 32,      ks * 16, lane);
            ldsm_x4(ah[1], Ahi, mw * 32 + 16, ks * 16, lane);
            ldsm_x4(al[0], Alo, mw * 32,      ks * 16, lane);
            ldsm_x4(al[1], Alo, mw * 32 + 16, ks * 16, lane);
#pragma unroll
            for (int f = 0; f < 6; f++) ldsm_x2(b[f], Whi, (f * 2 + nw) * 8, ks * 16, lane);
            mma_all<ALT>(accA, accH, ah, b);
            mma_all<ALT>(accA, accH, al, b);
#pragma unroll
            for (int f = 0; f < 6; f++) ldsm_x2(b[f], Wlo2, (f * 2 + nw) * 8, ks * 16, lane);
            mma_all<ALT>(accA, accH, ah, b);
        }
    }
}

// ---------------------------------------------------------------------------
// Warp-specialized fused GRU cell (320 threads).
// mode 0: gate epilogue; mode 1: raw input-gates -> gi_out.
// ---------------------------------------------------------------------------
__global__ __launch_bounds__(320) void gru_mma4(
    const float* __restrict__ X1, int ld1, int k1,
    const float* __restrict__ Hin, int htiles,
    const __nv_bfloat16* __restrict__ wpack,
    long wih_off, int wih_ldp, long whh_off,
    const float* __restrict__ gi_ext,
    const float* __restrict__ wdyn,
    const float* __restrict__ xdyn, int ld_dyn,
    const float* __restrict__ bih, const float* __restrict__ bhh,
    float* __restrict__ Hout, float* __restrict__ gi_out, int B, int mode) {
    extern __shared__ char sm_[];
    float* gbuf = (float*)sm_;
    float* wd_s = (float*)(sm_ + WD_OFF);

    const int tid = threadIdx.x;
    const int lane = tid & 31;
    const int w = tid >> 5;
    const int m0 = blockIdx.x * 128;
    const int n0 = blockIdx.y * 32;
    const int C = k1 + htiles;

    if (wdyn != nullptr) {
        for (int i = tid; i < 768; i += T_ALL) {
            int rr = i >> 3, q = i & 7;
            int p = rr >> 5, c = rr & 31;
            wd_s[i] = wdyn[((size_t)(p * 256) + n0 + c) * 8 + q];
        }
    }

    float accA[2][6][4];
    float accH[2][2][4];
#pragma unroll
    for (int mf = 0; mf < 2; mf++) {
#pragma unroll
        for (int f = 0; f < 6; f++)
#pragma unroll
            for (int u = 0; u < 4; u++) accA[mf][f][u] = 0.f;
#pragma unroll
        for (int f = 0; f < 2; f++)
#pragma unroll
            for (int u = 0; u < 4; u++) accH[mf][f][u] = 0.f;
    }

    if (w >= 8) {
        // -------- producer warps (64 threads) --------
        const int p = tid - 256;
        for (int c = 0; c < C; c++) {
            if (c >= 2) bar_sync(B_EMPTY0 + (c & 1), T_ALL);
            const float* X; int ldx, kk; const __nv_bfloat16 *wh, *wl; int ldw;
            if (c < k1) {
                X = X1; ldx = ld1; kk = c * 64;
                wh = wpack + wih_off; wl = wpack + WTOT + wih_off; ldw = wih_ldp;
            } else {
                X = Hin; ldx = 256; kk = (c - k1) * 64;
                wh = wpack + whh_off; wl = wpack + WTOT + whh_off; ldw = 256;
            }
            char* Ab = sm_ + ((c & 1) ? A1_OFF : A0_OFF);
            __nv_bfloat16* Wb = (__nv_bfloat16*)(sm_ + ((c & 1) ? W1_OFF : W0_OFF));
            for (int i = p; i < 768; i += NPROD) {
                int r = i >> 3, q = i & 7;
                int grow = (r >> 5) * 256 + n0 + (r & 31);
                size_t so = (size_t)grow * ldw + kk + q * 8;
                cp16(Wb + (size_t)r * STR + q * 8, wh + so);
                cp16(Wb + WHALF + (size_t)r * STR + q * 8, wl + so);
            }
            __nv_bfloat16* Ahi = (__nv_bfloat16*)Ab;
            __nv_bfloat16* Alo = (__nv_bfloat16*)(Ab + 18432);
            for (int i = p; i < 2048; i += NPROD) {
                int r = i >> 4, cc = (i & 15) * 4;
                int m = m0 + r;
                float4 v = make_float4(0.f, 0.f, 0.f, 0.f);
                if (m < B) v = *(const float4*)(X + (size_t)m * ldx + kk + cc);
                __nv_bfloat162 h0 = __floats2bfloat162_rn(v.x, v.y);
                __nv_bfloat162 h1 = __floats2bfloat162_rn(v.z, v.w);
                __nv_bfloat162 l0 = __floats2bfloat162_rn(v.x - __bfloat162float(h0.x),
                                                          v.y - __bfloat162float(h0.y));
                __nv_bfloat162 l1 = __floats2bfloat162_rn(v.z - __bfloat162float(h1.x),
                                                          v.w - __bfloat162float(h1.y));
                uint2 hh = make_uint2(*(uint32_t*)&h0, *(uint32_t*)&h1);
                uint2 ll = make_uint2(*(uint32_t*)&l0, *(uint32_t*)&l1);
                *(uint2*)(Ahi + (size_t)r * STR + cc) = hh;
                *(uint2*)(Alo + (size_t)r * STR + cc) = ll;
            }
            cp_commit();
            if (c >= 1) {
                cp_wait1();
                __threadfence_block();
                bar_arrive(B_FULL0 + ((c - 1) & 1), T_ALL);
            }
        }
        if (C >= 1) {
            cp_wait0();
            __threadfence_block();
            bar_arrive(B_FULL0 + ((C - 1) & 1), T_ALL);
        }
    } else {
        // -------- consumer warps (256 threads) --------
        const int mw = w >> 1;
        const int nw = w & 1;
        for (int c = 0; c < C; c++) {
            bar_sync(B_FULL0 + (c & 1), T_ALL);
            char* Ab = sm_ + ((c & 1) ? A1_OFF : A0_OFF);
            char* Wb = sm_ + ((c & 1) ? W1_OFF : W0_OFF);
            if (c >= k1) tile_mma4<true>(Ab, Wb, accA, accH, mw, nw, lane);
            else         tile_mma4<false>(Ab, Wb, accA, accH, mw, nw, lane);
            bar_arrive(B_EMPTY0 + (c & 1), T_ALL);
        }
    }

    // ---- scatter accumulators to gate buffer (aliases A buffers) ----
    __syncthreads();
    if (w < 8) {
        const int mw = w >> 1;
        const int nw = w & 1;
        int r0 = mw * 32 + (lane >> 2);
        int cl = (lane & 3) * 2;
#pragma unroll
        for (int mf = 0; mf < 2; mf++) {
#pragma unroll
            for (int f = 0; f < 6; f++) {
                int gf = f * 2 + nw;
                int p = gf >> 2;
                int col = ((gf * 8) & 31) + cl;
                int rr = r0 + mf * 16;
                float* g0 = gbuf + ((size_t)(p * 128 + rr)) * 36 + col;
                g0[0] = accA[mf][f][0]; g0[1] = accA[mf][f][1];
                g0[8 * 36] = accA[mf][f][2]; g0[8 * 36 + 1] = accA[mf][f][3];
                if (f >= 4) {
                    float* g1 = gbuf + ((size_t)(3 * 128 + rr)) * 36 + col;
                    g1[0] = accH[mf][f - 4][0]; g1[1] = accH[mf][f - 4][1];
                    g1[8 * 36] = accH[mf][f - 4][2]; g1[8 * 36 + 1] = accH[mf][f - 4][3];
                }
            }
        }
    }
    __syncthreads();

    if (mode == 1) {
        for (int i = tid; i < 3 * 128 * 32; i += T_ALL) {
            int p = i >> 12; int rem = i & 4095;
            int row = rem >> 5; int col = rem & 31;
            int m = m0 + row;
            if (m < B)
                gi_out[(size_t)m * 768 + p * 256 + n0 + col] =
                    gbuf[(size_t)(p * 128 + row) * 36 + col];
        }
        return;
    }

    // ---- gate epilogue (first 256 threads) ----
    if (tid < 256) {
        int row = tid >> 1;
        int m = m0 + row;
        int cbase = (tid & 1) * 16;
        bool valid = (m < B);
        float xd[6];
#pragma unroll
        for (int q = 0; q < 6; q++) xd[q] = 0.f;
        if (wdyn != nullptr && valid) {
#pragma unroll
            for (int q = 0; q < 6; q++) xd[q] = xdyn[(size_t)m * ld_dyn + q];
        }
        float ov[16];
#pragma unroll
        for (int c4 = 0; c4 < 4; c4++) {
            int col = cbase + c4 * 4;
            int jg = n0 + col;
            float grv[4], gzv[4], giv[4], ghv[4], hpv[4];
            *(float4*)grv = *(float4*)(gbuf + (size_t)(0 * 128 + row) * 36 + col);
            *(float4*)gzv = *(float4*)(gbuf + (size_t)(1 * 128 + row) * 36 + col);
            *(float4*)giv = *(float4*)(gbuf + (size_t)(2 * 128 + row) * 36 + col);
            *(float4*)ghv = *(float4*)(gbuf + (size_t)(3 * 128 + row) * 36 + col);
            if (valid) *(float4*)hpv = *(const float4*)(Hin + (size_t)m * 256 + jg);
            else { hpv[0] = hpv[1] = hpv[2] = hpv[3] = 0.f; }
            if (gi_ext != nullptr && valid) {
                float e0[4], e1[4], e2[4];
                *(float4*)e0 = *(const float4*)(gi_ext + (size_t)m * 768 + jg);
                *(float4*)e1 = *(const float4*)(gi_ext + (size_t)m * 768 + 256 + jg);
                *(float4*)e2 = *(const float4*)(gi_ext + (size_t)m * 768 + 512 + jg);
#pragma unroll
                for (int cc = 0; cc < 4; cc++) {
                    grv[cc] += e0[cc]; gzv[cc] += e1[cc]; giv[cc] += e2[cc];
                }
            }
            if (wdyn != nullptr) {
#pragma unroll
                for (int cc = 0; cc < 4; cc++) {
                    int cl_ = col + cc;
                    const float* w0 = wd_s + (0 * 32 + cl_) * 8;
                    const float* w1 = wd_s + (1 * 32 + cl_) * 8;
                    const float* w2 = wd_s + (2 * 32 + cl_) * 8;
#pragma unroll
                    for (int q = 0; q < 6; q++) {
                        grv[cc] += xd[q] * w0[q];
                        gzv[cc] += xd[q] * w1[q];
                        giv[cc] += xd[q] * w2[q];
                    }
                }
            }
#pragma unroll
            for (int cc = 0; cc < 4; cc++) {
                int j = jg + cc;
                float r_ = 1.f / (1.f + expf(-(grv[cc] + bih[j] + bhh[j])));
                float z_ = 1.f / (1.f + expf(-(gzv[cc] + bih[256 + j] + bhh[256 + j])));
                float n_ = tanhf(giv[cc] + bih[512 + j] + r_ * (ghv[cc] + bhh[512 + j]));
                ov[c4 * 4 + cc] = (1.f - z_) * n_ + z_ * hpv[cc];
            }
        }
        if (valid) {
#pragma unroll
            for (int c4 = 0; c4 < 4; c4++)
                *(float4*)(Hout + (size_t)m * 256 + n0 + cbase + c4 * 4) = *(float4*)(ov + c4 * 4);
        }
    }
}

// ---------------------------------------------------------------------------
// projection heads (R10, unchanged)
// ---------------------------------------------------------------------------
__device__ __forceinline__ void proj_scatter(float (&accA)[2][6][4], float* D1, int n0,
                                             const float* __restrict__ p1b,
                                             const float* __restrict__ a1b,
                                             int mw, int nw, int lane) {
    int r0 = mw * 32 + (lane >> 2);
    int cl = (lane & 3) * 2;
#pragma unroll
    for (int mf = 0; mf < 2; mf++)
#pragma unroll
        for (int f = 0; f < 6; f++) {
            int gf = f * 2 + nw;
            int colb = n0 + gf * 8 + cl;
            int rr = r0 + mf * 16;
#pragma unroll
            for (int jj = 0; jj < 2; jj++) {
                int col = colb + jj;
                float b = (col < 128) ? p1b[col] : a1b[col - 128];
                float v0 = accA[mf][f][jj] + b;
                float v1 = accA[mf][f][2 + jj] + b;
                D1[(size_t)rr * 196 + col] = v0 * normcdff(v0);
                D1[(size_t)(rr + 8) * 196 + col] = v1 * normcdff(v1);
            }
        }
}

__global__ __launch_bounds__(256) void proj_mma_kernel(
    const float* __restrict__ H,
    const __nv_bfloat16* __restrict__ wpack,
    const float* __restrict__ p1b, const float* __restrict__ a1b,
    const float* __restrict__ P2, const float* __restrict__ p2b,
    const float* __restrict__ A2, const float* __restrict__ a2b,
    float* __restrict__ out, float* __restrict__ dyn, int B, int tstep) {
    extern __shared__ char sm_[];
    __nv_bfloat16* Ahi = (__nv_bfloat16*)sm_;
    __nv_bfloat16* Alo = (__nv_bfloat16*)(sm_ + OFF_ALO);
    __nv_bfloat16* Wb0 = (__nv_bfloat16*)(sm_ + OFF_WB0);
    __nv_bfloat16* Wb1 = (__nv_bfloat16*)(sm_ + OFF_WB1);
    float* D1 = (float*)(sm_ + OFF_EXT);
    float* wsm = (float*)sm_;

    const int tid = threadIdx.x;
    const int lane = tid & 31;
    const int w = tid >> 5;
    const int mw = w >> 1;
    const int nw = w & 1;
    const int m0 = blockIdx.x * 128;

    float accA[2][6][4];
    float accH[2][2][4];
#pragma unroll
    for (int mf = 0; mf < 2; mf++) {
#pragma unroll
        for (int f = 0; f < 6; f++)
#pragma unroll
            for (int u = 0; u < 4; u++) accA[mf][f][u] = 0.f;
#pragma unroll
        for (int f = 0; f < 2; f++)
#pragma unroll
            for (int u = 0; u < 4; u++) accH[mf][f][u] = 0.f;
    }

    gemm_phase<false>(H, 256, 256, wpack + O_PA, wpack + WTOT + O_PA,
                      256, 32, m0, 0, B, Ahi, Alo, Wb0, Wb1, accA, accH);
    proj_scatter(accA, D1, 0, p1b, a1b, mw, nw, lane);
#pragma unroll
    for (int mf = 0; mf < 2; mf++)
#pragma unroll
        for (int f = 0; f < 6; f++)
#pragma unroll
            for (int u = 0; u < 4; u++) accA[mf][f][u] = 0.f;
    gemm_phase<false>(H, 256, 256, wpack + O_PA, wpack + WTOT + O_PA,
                      256, 32, m0, 96, B, Ahi, Alo, Wb0, Wb1, accA, accH);
    proj_scatter(accA, D1, 96, p1b, a1b, mw, nw, lane);
    __syncthreads();

    for (int i = tid; i < 512; i += 256) wsm[i] = P2[i];
    if (tid < 128) wsm[512 + tid] = A2[tid];
    if (tid < 4) wsm[640 + tid] = p2b[tid];
    if (tid < 2) wsm[644 + tid] = a2b[tid];
    __syncthreads();

#pragma unroll
    for (int it = 0; it < 2; it++) {
        int idx = tid + it * 256;
        int s = idx >> 2, o = idx & 3;
        float a = wsm[640 + o];
        const float* w2 = wsm + o * 128;
        const float* d = D1 + (size_t)s * 196;
#pragma unroll 8
        for (int k = 0; k < 128; k++) a += d[k] * w2[k];
        int m = m0 + s;
        if (m < B) {
            out[(size_t)m * 48 + tstep * 4 + o] = a;
            dyn[(size_t)m * 6 + (o < 2 ? o : o + 2)] = a;
        }
    }
    {
        int s = tid >> 1, o = tid & 1;
        float a = wsm[644 + o];
        const float* w2 = wsm + 512 + o * 64;
        const float* d = D1 + (size_t)s * 196 + 128;
#pragma unroll 8
        for (int k = 0; k < 64; k++) a += d[k] * w2[k];
        int m = m0 + s;
        if (m < B) dyn[(size_t)m * 6 + 2 + o] = a;
    }
}

// ---------------------------------------------------------------------------
extern "C" void kernel_launch(void* const* d_in, const int* in_sizes, int n_in,
                              void* d_out, int out_size) {
    const float* ctx      = (const float*)d_in[0];
    const float* obs_traj = (const float*)d_in[1];
    const float* obs_Me   = (const float*)d_in[2];
    const float* Wih0 = (const float*)d_in[3];
    const float* Whh0 = (const float*)d_in[4];
    const float* bih0 = (const float*)d_in[5];
    const float* bhh0 = (const float*)d_in[6];
    const float* Wih1 = (const float*)d_in[7];
    const float* Whh1 = (const float*)d_in[8];
    const float* bih1 = (const float*)d_in[9];
    const float* bhh1 = (const float*)d_in[10];
    const float* Wihs = (const float*)d_in[11];
    const float* Whhs = (const float*)d_in[12];
    const float* bihs = (const float*)d_in[13];
    const float* bhhs = (const float*)d_in[14];
    const float* P1  = (const float*)d_in[15];
    const float* p1b = (const float*)d_in[16];
    const float* P2  = (const float*)d_in[17];
    const float* p2b = (const float*)d_in[18];
    const float* A1  = (const float*)d_in[19];
    const float* a1b = (const float*)d_in[20];
    const float* A2  = (const float*)d_in[21];
    const float* a2b = (const float*)d_in[22];
    const float* Cw  = (const float*)d_in[23];
    const float* cb  = (const float*)d_in[24];
    float* out = (float*)d_out;

    int B = in_sizes[0] / CTXD;
    if (B > BMAX) B = BMAX;
    int T = in_sizes[1] / (2 * B);
    int TS = T - 1;

    float *h0a, *h0b, *h1a, *h1b, *obsin, *ctxp, *dynA, *dynB, *gictx, *wd0, *wdS;
    __nv_bfloat16* wpk;
    cudaGetSymbolAddress((void**)&h0a, g_h0a);
    cudaGetSymbolAddress((void**)&h0b, g_h0b);
    cudaGetSymbolAddress((void**)&h1a, g_h1a);
    cudaGetSymbolAddress((void**)&h1b, g_h1b);
    cudaGetSymbolAddress((void**)&obsin, g_obsin);
    cudaGetSymbolAddress((void**)&ctxp, g_ctxp);
    cudaGetSymbolAddress((void**)&dynA, g_dynA);
    cudaGetSymbolAddress((void**)&dynB, g_dynB);
    cudaGetSymbolAddress((void**)&gictx, g_gictx);
    cudaGetSymbolAddress((void**)&wd0, g_wdyn0);
    cudaGetSymbolAddress((void**)&wdS, g_wdynS);
    cudaGetSymbolAddress((void**)&wpk, g_wpack);

    cudaFuncSetAttribute(gru_mma4, cudaFuncAttributeMaxDynamicSharedMemorySize, GRU_SMEM);
    cudaFuncSetAttribute(proj_mma_kernel, cudaFuncAttributeMaxDynamicSharedMemorySize, PROJ_SMEM);

    pack_kernel<<<768, 256>>>(Whh0, 768, 256, 0, 256, 256, O_WHH0, wpk);
    pack_kernel<<<768, 256>>>(Wih1, 768, 256, 0, 256, 256, O_WIH1, wpk);
    pack_kernel<<<768, 256>>>(Whh1, 768, 256, 0, 256, 256, O_WHH1, wpk);
    pack_kernel<<<768, 256>>>(Whhs, 768, 256, 0, 256, 256, O_WHHS, wpk);
    pack_kernel<<<384, 256>>>(Wihs, 768, 134, 0, 128, 128, O_WCTX, wpk);
    pack_kernel<<<128, 256>>>(P1, 128, 256, 0, 256, 256, O_PA, wpk);
    pack_kernel<<<64, 256>>>(A1, 64, 256, 0, 256, 256, O_PA + 128L * 256, wpk);
    wdyn_pack_kernel<<<24, 256>>>(Wih0, 6, 0, wd0);
    wdyn_pack_kernel<<<24, 256>>>(Wihs, 134, 128, wdS);

    zero_kernel<<<264, 256>>>(h0a, B * HDIM);
    zero_kernel<<<264, 256>>>(h1a, B * HDIM);
    prep_kernel<<<(B + 255) / 256, 256>>>(obs_traj, obs_Me, obsin, dynA, B, T);
    ctx_kernel<<<(B + 63) / 64, 256>>>(ctx, Cw, cb, ctxp, B);

    dim3 cgrid((B + 127) / 128, 8);

    // hoisted decoder ctx input-gates: gi_ctx = ctxp @ Wihs[:, :128].T
    gru_mma4<<<cgrid, T_ALL, GRU_SMEM>>>(ctxp, 128, 2,
                                         nullptr, 0,
                                         wpk, O_WCTX, 128, 0L,
                                         nullptr, nullptr, nullptr, 0,
                                         bihs, bhhs, nullptr, gictx, B, 1);

    // encoder
    float *h0i = h0a, *h0o = h0b, *h1i = h1a, *h1o = h1b;
    for (int t = 0; t < TS; t++) {
        gru_mma4<<<cgrid, T_ALL, GRU_SMEM>>>(nullptr, 0, 0,
                                             h0i, (t > 0) ? 4 : 0,
                                             wpk, 0L, 0, O_WHH0,
                                             nullptr, wd0, obsin + (size_t)t * B * 6, 6,
                                             bih0, bhh0, h0o, nullptr, B, 0);
        gru_mma4<<<cgrid, T_ALL, GRU_SMEM>>>(h0o, 256, 4,
                                             h1i, (t > 0) ? 4 : 0,
                                             wpk, O_WIH1, 256, O_WHH1,
                                             nullptr, nullptr, nullptr, 0,
                                             bih1, bhh1, h1o, nullptr, B, 0);
        float* t0 = h0i; h0i = h0o; h0o = t0;
        float* t1 = h1i; h1i = h1o; h1o = t1;
    }

    // decoder
    float* dhi = h1i;
    float* dho = h1o;
    float* dyi = dynA;
    float* dyo = dynB;
    for (int s = 0; s < PRED; s++) {
        gru_mma4<<<cgrid, T_ALL, GRU_SMEM>>>(nullptr, 0, 0,
                                             dhi, 4,
                                             wpk, 0L, 0, O_WHHS,
                                             gictx, wdS, dyi, 6,
                                             bihs, bhhs, dho, nullptr, B, 0);
        proj_mma_kernel<<<(B + 127) / 128, 256, PROJ_SMEM>>>(dho, wpk, p1b, a1b,
                                                             P2, p2b, A2, a2b,
                                                             out, dyo, B, s);
        float* td = dhi; dhi = dho; dho = td;
        float* ty_ = dyi; dyi = dyo; dyo = ty_;
    }
}

// round 14
// speedup vs baseline: 2.3078x; 2.3078x over previous
#include <cuda_runtime.h>
#include <cuda_fp16.h>
#include <math.h>
#include <stdint.h>

// ---------------------------------------------------------------------------
// DirectRegressionHead: 2-layer GRU encoder (7 steps) + 12-step GRU decoder.
// B=32768, H=256, CTX=128, PRED=12.
// GRU/proj GEMMs: fp16x2 split (W = hi+lo fp16, A = fp16) via
// mma.sync.m16n8k16.f16, fp32 accumulate — 2 passes per chunk.
// R10 structure: 256 thr, N=32 gate-cols, 2 CTAs/SM, double-buffered
// cp.async weight staging (W prefetched one K=64 chunk ahead).
// ---------------------------------------------------------------------------

#define BMAX 32768
#define HDIM 256
#define CTXD 128
#define PRED 12
#define STR 72            // smem tile k-stride in halves (64 + 8 pad)
#define WHALF (96 * STR)  // elements between W hi and lo planes in one buffer

// packed weight layout (fp16 elements, hi plane; lo plane at +WTOT)
#define O_WHH0 0L          // 768 x 256
#define O_WIH1 196608L
#define O_WHH1 393216L
#define O_WHHS 589824L
#define O_WCTX 786432L     // 768 x 128  (Wihs cols 0..127)
#define O_PA   884736L     // 192 x 256  (P1 rows 0..127, A1 rows 128..191)
#define WTOT   933888L

// smem layout (bytes): Ahi 0 | Wb0 18432 | Wb1 46080 | ext 73728
// gbuf (73728B) aliases Ahi+Wb0+Wb1 exactly.
#define OFF_WB0 18432
#define OFF_WB1 46080
#define OFF_EXT 73728
#define GRU_SMEM 76800          // + wd_s 3072
#define PROJ_SMEM 174080        // + D1 100352

// --- static device scratch ---
__device__ float g_h0a[BMAX * HDIM];
__device__ float g_h0b[BMAX * HDIM];
__device__ float g_h1a[BMAX * HDIM];
__device__ float g_h1b[BMAX * HDIM];
__device__ float g_obsin[8 * BMAX * 6];
__device__ float g_ctxp[BMAX * CTXD];
__device__ float g_dynA[BMAX * 6];
__device__ float g_dynB[BMAX * 6];
__device__ float g_gictx[(size_t)BMAX * 768];
__device__ float g_wdyn0[768 * 8];
__device__ float g_wdynS[768 * 8];
__device__ __half g_wpack[2 * WTOT];

// ---------------- async-copy helpers ----------------
__device__ __forceinline__ void cp16(void* dst, const void* src) {
    uint32_t d = (uint32_t)__cvta_generic_to_shared(dst);
    asm volatile("cp.async.cg.shared.global [%0], [%1], 16;" :: "r"(d), "l"(src));
}
__device__ __forceinline__ void cp_commit() {
    asm volatile("cp.async.commit_group;");
}
__device__ __forceinline__ void cp_wait0() {
    asm volatile("cp.async.wait_group 0;");
}
__device__ __forceinline__ void cp_wait1() {
    asm volatile("cp.async.wait_group 1;");
}

// ---------------------------------------------------------------------------
__global__ void zero_kernel(float* __restrict__ p, int n) {
    int stride = gridDim.x * blockDim.x;
    for (int i = blockIdx.x * blockDim.x + threadIdx.x; i * 4 < n; i += stride)
        ((float4*)p)[i] = make_float4(0.f, 0.f, 0.f, 0.f);
}

// pack [rows, K] slice of src (row stride ld, col offset koff) -> hi/lo fp16
__global__ void pack_kernel(const float* __restrict__ W, int rows, int ld, int koff,
                            int K, int Kpad, long dst, __half* __restrict__ wp) {
    int i = blockIdx.x * blockDim.x + threadIdx.x;
    if (i >= rows * Kpad) return;
    int r = i / Kpad, k = i - r * Kpad;
    float v = (k < K) ? W[(size_t)r * ld + koff + k] : 0.f;
    __half h = __float2half(v);
    wp[dst + i] = h;
    wp[WTOT + dst + i] = __float2half(v - __half2float(h));
}

__global__ void wdyn_pack_kernel(const float* __restrict__ src, int ld, int koff,
                                 float* __restrict__ dst) {
    int i = blockIdx.x * blockDim.x + threadIdx.x;
    if (i >= 768 * 8) return;
    int r = i >> 3, q = i & 7;
    dst[i] = (q < 6) ? src[(size_t)r * ld + koff + q] : 0.f;
}

// ---------------------------------------------------------------------------
__global__ void prep_kernel(const float* __restrict__ traj,
                            const float* __restrict__ me,
                            float* __restrict__ obsin,
                            float* __restrict__ dyn, int B, int T) {
    int b = blockIdx.x * blockDim.x + threadIdx.x;
    if (b >= B) return;
    float vx[8], vy[8], mx[8], my_[8];
    int TS = T - 1;
    if (TS > 8) TS = 8;
    for (int t = 0; t < TS; t++) {
        vx[t]  = traj[((size_t)(t + 1) * B + b) * 2 + 0] - traj[((size_t)t * B + b) * 2 + 0];
        vy[t]  = traj[((size_t)(t + 1) * B + b) * 2 + 1] - traj[((size_t)t * B + b) * 2 + 1];
        mx[t]  = me[((size_t)(t + 1) * B + b) * 2 + 0] - me[((size_t)t * B + b) * 2 + 0];
        my_[t] = me[((size_t)(t + 1) * B + b) * 2 + 1] - me[((size_t)t * B + b) * 2 + 1];
    }
    for (int t = 0; t < TS; t++) {
        int ta = (t == 0) ? 1 : t;
        float ax = vx[ta] - vx[ta - 1];
        float ay = vy[ta] - vy[ta - 1];
        float* o = obsin + ((size_t)t * B + b) * 6;
        o[0] = vx[t]; o[1] = vy[t];
        o[2] = mx[t]; o[3] = my_[t];
        o[4] = ax;    o[5] = ay;
    }
    dyn[(size_t)b * 6 + 0] = vx[TS - 1];
    dyn[(size_t)b * 6 + 1] = vy[TS - 1];
    dyn[(size_t)b * 6 + 2] = vx[TS - 1] - vx[TS - 2];
    dyn[(size_t)b * 6 + 3] = vy[TS - 1] - vy[TS - 2];
    dyn[(size_t)b * 6 + 4] = mx[TS - 1];
    dyn[(size_t)b * 6 + 5] = my_[TS - 1];
}

// ---------------------------------------------------------------------------
__global__ __launch_bounds__(256) void ctx_kernel(const float* __restrict__ ctx,
                                                  const float* __restrict__ Cw,
                                                  const float* __restrict__ cb,
                                                  float* __restrict__ outp, int B) {
    __shared__ float Cs[64][128];
    __shared__ float Wc[16][128];
    int tid = threadIdx.x;
    int m0 = blockIdx.x * 64;
    for (int i = tid; i < 64 * 128 / 4; i += 256) {
        int m = m0 + (i * 4) / 128;
        float4 v = make_float4(0.f, 0.f, 0.f, 0.f);
        if (m < B) v = *(const float4*)&ctx[(size_t)m0 * 128 + i * 4];
        ((float4*)Cs)[i] = v;
    }
    __syncthreads();
    int w = tid >> 5, lane = tid & 31;
    float acc[8][4];
#pragma unroll
    for (int i = 0; i < 8; i++)
#pragma unroll
        for (int u = 0; u < 4; u++) acc[i][u] = 0.f;

    for (int k0 = 0; k0 < 128; k0 += 16) {
        for (int i = tid; i < 16 * 128; i += 256) {
            int kk = i & 15, u = i >> 4;
            Wc[kk][u] = Cw[(size_t)u * 128 + k0 + kk];
        }
        __syncthreads();
#pragma unroll
        for (int kk = 0; kk < 16; kk++) {
            float wv[4];
#pragma unroll
            for (int u = 0; u < 4; u++) wv[u] = Wc[kk][lane * 4 + u];
#pragma unroll
            for (int i = 0; i < 8; i++) {
                float a = Cs[w * 8 + i][k0 + kk];
#pragma unroll
                for (int u = 0; u < 4; u++) acc[i][u] += a * wv[u];
            }
        }
        __syncthreads();
    }
#pragma unroll
    for (int i = 0; i < 8; i++) {
        int m = m0 + w * 8 + i;
        if (m >= B) continue;
#pragma unroll
        for (int u = 0; u < 4; u++) {
            int ug = lane * 4 + u;
            outp[(size_t)m * 128 + ug] = acc[i][u] + cb[ug];
        }
    }
}

// ---------------------------------------------------------------------------
// tensor-core helpers (fp16)
// ---------------------------------------------------------------------------
__device__ __forceinline__ void mma_f16(float* c, const uint32_t* a, uint32_t b0, uint32_t b1) {
    asm volatile(
        "mma.sync.aligned.m16n8k16.row.col.f32.f16.f16.f32 "
        "{%0,%1,%2,%3}, {%4,%5,%6,%7}, {%8,%9}, {%0,%1,%2,%3};\n"
        : "+f"(c[0]), "+f"(c[1]), "+f"(c[2]), "+f"(c[3])
        : "r"(a[0]), "r"(a[1]), "r"(a[2]), "r"(a[3]), "r"(b0), "r"(b1));
}

__device__ __forceinline__ void ldsm_x4(uint32_t* r, const __half* base,
                                        int row, int col, int lane) {
    int g = lane >> 3, rr = lane & 7;
    const __half* p = base + (size_t)(row + (g & 1) * 8 + rr) * STR + col + (g >> 1) * 8;
    uint32_t addr = (uint32_t)__cvta_generic_to_shared(p);
    asm volatile("ldmatrix.sync.aligned.m8n8.x4.shared.b16 {%0,%1,%2,%3}, [%4];"
                 : "=r"(r[0]), "=r"(r[1]), "=r"(r[2]), "=r"(r[3]) : "r"(addr));
}

__device__ __forceinline__ void ldsm_x2(uint32_t* r, const __half* base,
                                        int row, int col, int lane) {
    int l = lane & 15;
    int g = l >> 3, rr = l & 7;
    const __half* p = base + (size_t)(row + rr) * STR + col + g * 8;
    uint32_t addr = (uint32_t)__cvta_generic_to_shared(p);
    asm volatile("ldmatrix.sync.aligned.m8n8.x2.shared.b16 {%0,%1}, [%2];"
                 : "=r"(r[0]), "=r"(r[1]) : "r"(addr));
}

template<bool ALT>
__device__ __forceinline__ void mma_all(float (&accA)[2][6][4], float (&accH)[2][2][4],
                                        uint32_t a[2][4], uint32_t b[6][2]) {
#pragma unroll
    for (int mf = 0; mf < 2; mf++)
#pragma unroll
        for (int f = 0; f < 6; f++) {
            float* c = (ALT && f >= 4) ? accH[mf][f - 4] : accA[mf][f];
            mma_f16(c, a[mf], b[f][0], b[f][1]);
        }
}

// acc += fp16(X[128 x K]) @ (Whi+Wlo)[96 x K]^T    (2 passes)
// K multiple of 64; X row stride multiple of 4.
// W double-buffered via cp.async, prefetched one chunk ahead.
template<bool ALT>
__device__ __forceinline__ void gemm_phase(
    const float* __restrict__ X, int ldx, int K,
    const __half* __restrict__ wHi, const __half* __restrict__ wLo,
    int ldwp, int plane_stride,
    int m0, int n0, int B,
    __half* Ahi, __half* Wb0, __half* Wb1,
    float (&accA)[2][6][4], float (&accH)[2][2][4]) {
    const int tid = threadIdx.x;
    const int lane = tid & 31;
    const int w = tid >> 5;
    const int mw = w >> 1;
    const int nw = w & 1;
    const int nch = K / 64;

    // prologue: prefetch W chunk 0 into Wb0
    for (int i = tid; i < 768; i += 256) {
        int r = i >> 3, q = i & 7;
        int grow = (r >> 5) * plane_stride + n0 + (r & 31);
        size_t so = (size_t)grow * ldwp + q * 8;
        cp16(Wb0 + (size_t)r * STR + q * 8, wHi + so);
        cp16(Wb0 + WHALF + (size_t)r * STR + q * 8, wLo + so);
    }
    cp_commit();

    for (int c = 0; c < nch; c++) {
        int k0 = c * 64;
        __syncthreads();
        // stage A (single fp16 plane)
        for (int i = tid; i < 2048; i += 256) {
            int r = i >> 4, cc = (i & 15) * 4;
            int m = m0 + r;
            float4 v = make_float4(0.f, 0.f, 0.f, 0.f);
            if (m < B) v = *(const float4*)(X + (size_t)m * ldx + k0 + cc);
            __half2 h0 = __floats2half2_rn(v.x, v.y);
            __half2 h1 = __floats2half2_rn(v.z, v.w);
            *(__half2*)(Ahi + (size_t)r * STR + cc)     = h0;
            *(__half2*)(Ahi + (size_t)r * STR + cc + 2) = h1;
        }
        // prefetch W chunk c+1 into the other buffer
        if (c + 1 < nch) {
            __half* Wd = (c & 1) ? Wb0 : Wb1;   // (c+1)&1
            int k1 = (c + 1) * 64;
            for (int i = tid; i < 768; i += 256) {
                int r = i >> 3, q = i & 7;
                int grow = (r >> 5) * plane_stride + n0 + (r & 31);
                size_t so = (size_t)grow * ldwp + k1 + q * 8;
                cp16(Wd + (size_t)r * STR + q * 8, wHi + so);
                cp16(Wd + WHALF + (size_t)r * STR + q * 8, wLo + so);
            }
            cp_commit();
            cp_wait1();
        } else {
            cp_wait0();
        }
        __syncthreads();
        const __half* Whi = (c & 1) ? Wb1 : Wb0;
        const __half* Wlo2 = Whi + WHALF;
#pragma unroll
        for (int ks = 0; ks < 4; ks++) {
            uint32_t ah[2][4], b[6][2];
            ldsm_x4(ah[0], Ahi, mw * 32,      ks * 16, lane);
            ldsm_x4(ah[1], Ahi, mw * 32 + 16, ks * 16, lane);
#pragma unroll
            for (int f = 0; f < 6; f++) ldsm_x2(b[f], Whi, (f * 2 + nw) * 8, ks * 16, lane);
            mma_all<ALT>(accA, accH, ah, b);   // A * Whi
#pragma unroll
            for (int f = 0; f < 6; f++) ldsm_x2(b[f], Wlo2, (f * 2 + nw) * 8, ks * 16, lane);
            mma_all<ALT>(accA, accH, ah, b);   // A * Wlo
        }
    }
}

// ---------------------------------------------------------------------------
// Fused GRU cell. mode 0: gate epilogue; mode 1: raw input-gates -> gi_out.
// ---------------------------------------------------------------------------
__global__ __launch_bounds__(256) void gru_mma_kernel(
    const float* __restrict__ X1, int ld1, int k1,
    const float* __restrict__ Hin, int do_hidden,
    const __half* __restrict__ wpack,
    long wih_off, int wih_ldp, long whh_off,
    const float* __restrict__ gi_ext,
    const float* __restrict__ wdyn,
    const float* __restrict__ xdyn, int ld_dyn,
    const float* __restrict__ bih, const float* __restrict__ bhh,
    float* __restrict__ Hout, float* __restrict__ gi_out, int B, int mode) {
    extern __shared__ char sm_[];
    __half* Ahi = (__half*)sm_;
    __half* Wb0 = (__half*)(sm_ + OFF_WB0);
    __half* Wb1 = (__half*)(sm_ + OFF_WB1);
    float* gbuf = (float*)sm_;
    float* wd_s = (float*)(sm_ + OFF_EXT);

    const int tid = threadIdx.x;
    const int lane = tid & 31;
    const int w = tid >> 5;
    const int mw = w >> 1;
    const int nw = w & 1;
    const int m0 = blockIdx.x * 128;
    const int n0 = blockIdx.y * 32;

    if (wdyn != nullptr) {
        for (int i = tid; i < 768; i += 256) {
            int rr = i >> 3, q = i & 7;
            int p = rr >> 5, c = rr & 31;
            wd_s[i] = wdyn[((size_t)(p * 256) + n0 + c) * 8 + q];
        }
    }

    float accA[2][6][4];
    float accH[2][2][4];
#pragma unroll
    for (int mf = 0; mf < 2; mf++) {
#pragma unroll
        for (int f = 0; f < 6; f++)
#pragma unroll
            for (int u = 0; u < 4; u++) accA[mf][f][u] = 0.f;
#pragma unroll
        for (int f = 0; f < 2; f++)
#pragma unroll
            for (int u = 0; u < 4; u++) accH[mf][f][u] = 0.f;
    }

    if (X1 != nullptr)
        gemm_phase<false>(X1, ld1, k1, wpack + wih_off, wpack + WTOT + wih_off,
                          wih_ldp, 256, m0, n0, B, Ahi, Wb0, Wb1, accA, accH);
    if (do_hidden)
        gemm_phase<true>(Hin, 256, 256, wpack + whh_off, wpack + WTOT + whh_off,
                         256, 256, m0, n0, B, Ahi, Wb0, Wb1, accA, accH);

    // ---- scatter accumulators to gate buffer ----
    __syncthreads();
    {
        int r0 = mw * 32 + (lane >> 2);
        int cl = (lane & 3) * 2;
#pragma unroll
        for (int mf = 0; mf < 2; mf++) {
#pragma unroll
            for (int f = 0; f < 6; f++) {
                int gf = f * 2 + nw;
                int p = gf >> 2;
                int col = ((gf * 8) & 31) + cl;
                int rr = r0 + mf * 16;
                float* g0 = gbuf + ((size_t)(p * 128 + rr)) * 36 + col;
                g0[0] = accA[mf][f][0]; g0[1] = accA[mf][f][1];
                g0[8 * 36] = accA[mf][f][2]; g0[8 * 36 + 1] = accA[mf][f][3];
                if (f >= 4) {
                    float* g1 = gbuf + ((size_t)(3 * 128 + rr)) * 36 + col;
                    g1[0] = accH[mf][f - 4][0]; g1[1] = accH[mf][f - 4][1];
                    g1[8 * 36] = accH[mf][f - 4][2]; g1[8 * 36 + 1] = accH[mf][f - 4][3];
                }
            }
        }
    }
    __syncthreads();

    if (mode == 1) {
        for (int i = tid; i < 3 * 128 * 32; i += 256) {
            int p = i >> 12; int rem = i & 4095;
            int row = rem >> 5; int col = rem & 31;
            int m = m0 + row;
            if (m < B)
                gi_out[(size_t)m * 768 + p * 256 + n0 + col] =
                    gbuf[(size_t)(p * 128 + row) * 36 + col];
        }
        return;
    }

    // ---- gate epilogue ----
    {
        int row = tid >> 1;
        int m = m0 + row;
        int cbase = (tid & 1) * 16;
        bool valid = (m < B);
        float xd[6];
#pragma unroll
        for (int q = 0; q < 6; q++) xd[q] = 0.f;
        if (wdyn != nullptr && valid) {
#pragma unroll
            for (int q = 0; q < 6; q++) xd[q] = xdyn[(size_t)m * ld_dyn + q];
        }
        float ov[16];
#pragma unroll
        for (int c4 = 0; c4 < 4; c4++) {
            int col = cbase + c4 * 4;
            int jg = n0 + col;
            float grv[4], gzv[4], giv[4], ghv[4], hpv[4];
            *(float4*)grv = *(float4*)(gbuf + (size_t)(0 * 128 + row) * 36 + col);
            *(float4*)gzv = *(float4*)(gbuf + (size_t)(1 * 128 + row) * 36 + col);
            *(float4*)giv = *(float4*)(gbuf + (size_t)(2 * 128 + row) * 36 + col);
            *(float4*)ghv = *(float4*)(gbuf + (size_t)(3 * 128 + row) * 36 + col);
            if (valid) *(float4*)hpv = *(const float4*)(Hin + (size_t)m * 256 + jg);
            else { hpv[0] = hpv[1] = hpv[2] = hpv[3] = 0.f; }
            if (gi_ext != nullptr && valid) {
                float e0[4], e1[4], e2[4];
                *(float4*)e0 = *(const float4*)(gi_ext + (size_t)m * 768 + jg);
                *(float4*)e1 = *(const float4*)(gi_ext + (size_t)m * 768 + 256 + jg);
                *(float4*)e2 = *(const float4*)(gi_ext + (size_t)m * 768 + 512 + jg);
#pragma unroll
                for (int cc = 0; cc < 4; cc++) {
                    grv[cc] += e0[cc]; gzv[cc] += e1[cc]; giv[cc] += e2[cc];
                }
            }
            if (wdyn != nullptr) {
#pragma unroll
                for (int cc = 0; cc < 4; cc++) {
                    int cl_ = col + cc;
                    const float* w0 = wd_s + (0 * 32 + cl_) * 8;
                    const float* w1 = wd_s + (1 * 32 + cl_) * 8;
                    const float* w2 = wd_s + (2 * 32 + cl_) * 8;
#pragma unroll
                    for (int q = 0; q < 6; q++) {
                        grv[cc] += xd[q] * w0[q];
                        gzv[cc] += xd[q] * w1[q];
                        giv[cc] += xd[q] * w2[q];
                    }
                }
            }
#pragma unroll
            for (int cc = 0; cc < 4; cc++) {
                int j = jg + cc;
                float r_ = 1.f / (1.f + expf(-(grv[cc] + bih[j] + bhh[j])));
                float z_ = 1.f / (1.f + expf(-(gzv[cc] + bih[256 + j] + bhh[256 + j])));
                float n_ = tanhf(giv[cc] + bih[512 + j] + r_ * (ghv[cc] + bhh[512 + j]));
                ov[c4 * 4 + cc] = (1.f - z_) * n_ + z_ * hpv[cc];
            }
        }
        if (valid) {
#pragma unroll
            for (int c4 = 0; c4 < 4; c4++)
                *(float4*)(Hout + (size_t)m * 256 + n0 + cbase + c4 * 4) = *(float4*)(ov + c4 * 4);
        }
    }
}

// ---------------------------------------------------------------------------
// projection heads: stage1 [B,192] = GELU(H @ [P1;A1]^T + b), stage2 heads.
// ---------------------------------------------------------------------------
__device__ __forceinline__ void proj_scatter(float (&accA)[2][6][4], float* D1, int n0,
                                             const float* __restrict__ p1b,
                                             const float* __restrict__ a1b,
                                             int mw, int nw, int lane) {
    int r0 = mw * 32 + (lane >> 2);
    int cl = (lane & 3) * 2;
#pragma unroll
    for (int mf = 0; mf < 2; mf++)
#pragma unroll
        for (int f = 0; f < 6; f++) {
            int gf = f * 2 + nw;
            int colb = n0 + gf * 8 + cl;
            int rr = r0 + mf * 16;
#pragma unroll
            for (int jj = 0; jj < 2; jj++) {
                int col = colb + jj;
                float b = (col < 128) ? p1b[col] : a1b[col - 128];
                float v0 = accA[mf][f][jj] + b;
                float v1 = accA[mf][f][2 + jj] + b;
                D1[(size_t)rr * 196 + col] = v0 * normcdff(v0);
                D1[(size_t)(rr + 8) * 196 + col] = v1 * normcdff(v1);
            }
        }
}

__global__ __launch_bounds__(256) void proj_mma_kernel(
    const float* __restrict__ H,
    const __half* __restrict__ wpack,
    const float* __restrict__ p1b, const float* __restrict__ a1b,
    const float* __restrict__ P2, const float* __restrict__ p2b,
    const float* __restrict__ A2, const float* __restrict__ a2b,
    float* __restrict__ out, float* __restrict__ dyn, int B, int tstep) {
    extern __shared__ char sm_[];
    __half* Ahi = (__half*)sm_;
    __half* Wb0 = (__half*)(sm_ + OFF_WB0);
    __half* Wb1 = (__half*)(sm_ + OFF_WB1);
    float* D1 = (float*)(sm_ + OFF_EXT);
    float* wsm = (float*)sm_;   // reused after GEMM for head weights

    const int tid = threadIdx.x;
    const int lane = tid & 31;
    const int w = tid >> 5;
    const int mw = w >> 1;
    const int nw = w & 1;
    const int m0 = blockIdx.x * 128;

    float accA[2][6][4];
    float accH[2][2][4];
#pragma unroll
    for (int mf = 0; mf < 2; mf++) {
#pragma unroll
        for (int f = 0; f < 6; f++)
#pragma unroll
            for (int u = 0; u < 4; u++) accA[mf][f][u] = 0.f;
#pragma unroll
        for (int f = 0; f < 2; f++)
#pragma unroll
            for (int u = 0; u < 4; u++) accH[mf][f][u] = 0.f;
    }

    gemm_phase<false>(H, 256, 256, wpack + O_PA, wpack + WTOT + O_PA,
                      256, 32, m0, 0, B, Ahi, Wb0, Wb1, accA, accH);
    proj_scatter(accA, D1, 0, p1b, a1b, mw, nw, lane);
#pragma unroll
    for (int mf = 0; mf < 2; mf++)
#pragma unroll
        for (int f = 0; f < 6; f++)
#pragma unroll
            for (int u = 0; u < 4; u++) accA[mf][f][u] = 0.f;
    gemm_phase<false>(H, 256, 256, wpack + O_PA, wpack + WTOT + O_PA,
                      256, 32, m0, 96, B, Ahi, Wb0, Wb1, accA, accH);
    proj_scatter(accA, D1, 96, p1b, a1b, mw, nw, lane);
    __syncthreads();

    // stage head weights into (now free) tile smem
    for (int i = tid; i < 512; i += 256) wsm[i] = P2[i];
    if (tid < 128) wsm[512 + tid] = A2[tid];
    if (tid < 4) wsm[640 + tid] = p2b[tid];
    if (tid < 2) wsm[644 + tid] = a2b[tid];
    __syncthreads();

    // delta head: 128 rows x 4 outs, K=128
#pragma unroll
    for (int it = 0; it < 2; it++) {
        int idx = tid + it * 256;
        int s = idx >> 2, o = idx & 3;
        float a = wsm[640 + o];
        const float* w2 = wsm + o * 128;
        const float* d = D1 + (size_t)s * 196;
#pragma unroll 8
        for (int k = 0; k < 128; k++) a += d[k] * w2[k];
        int m = m0 + s;
        if (m < B) {
            out[(size_t)m * 48 + tstep * 4 + o] = a;
            dyn[(size_t)m * 6 + (o < 2 ? o : o + 2)] = a;
        }
    }
    // accel head: 128 rows x 2 outs, K=64
    {
        int s = tid >> 1, o = tid & 1;
        float a = wsm[644 + o];
        const float* w2 = wsm + 512 + o * 64;
        const float* d = D1 + (size_t)s * 196 + 128;
#pragma unroll 8
        for (int k = 0; k < 64; k++) a += d[k] * w2[k];
        int m = m0 + s;
        if (m < B) dyn[(size_t)m * 6 + 2 + o] = a;
    }
}

// ---------------------------------------------------------------------------
extern "C" void kernel_launch(void* const* d_in, const int* in_sizes, int n_in,
                              void* d_out, int out_size) {
    const float* ctx      = (const float*)d_in[0];
    const float* obs_traj = (const float*)d_in[1];
    const float* obs_Me   = (const float*)d_in[2];
    const float* Wih0 = (const float*)d_in[3];
    const float* Whh0 = (const float*)d_in[4];
    const float* bih0 = (const float*)d_in[5];
    const float* bhh0 = (const float*)d_in[6];
    const float* Wih1 = (const float*)d_in[7];
    const float* Whh1 = (const float*)d_in[8];
    const float* bih1 = (const float*)d_in[9];
    const float* bhh1 = (const float*)d_in[10];
    const float* Wihs = (const float*)d_in[11];
    const float* Whhs = (const float*)d_in[12];
    const float* bihs = (const float*)d_in[13];
    const float* bhhs = (const float*)d_in[14];
    const float* P1  = (const float*)d_in[15];
    const float* p1b = (const float*)d_in[16];
    const float* P2  = (const float*)d_in[17];
    const float* p2b = (const float*)d_in[18];
    const float* A1  = (const float*)d_in[19];
    const float* a1b = (const float*)d_in[20];
    const float* A2  = (const float*)d_in[21];
    const float* a2b = (const float*)d_in[22];
    const float* Cw  = (const float*)d_in[23];
    const float* cb  = (const float*)d_in[24];
    float* out = (float*)d_out;

    int B = in_sizes[0] / CTXD;
    if (B > BMAX) B = BMAX;
    int T = in_sizes[1] / (2 * B);
    int TS = T - 1;

    float *h0a, *h0b, *h1a, *h1b, *obsin, *ctxp, *dynA, *dynB, *gictx, *wd0, *wdS;
    __half* wpk;
    cudaGetSymbolAddress((void**)&h0a, g_h0a);
    cudaGetSymbolAddress((void**)&h0b, g_h0b);
    cudaGetSymbolAddress((void**)&h1a, g_h1a);
    cudaGetSymbolAddress((void**)&h1b, g_h1b);
    cudaGetSymbolAddress((void**)&obsin, g_obsin);
    cudaGetSymbolAddress((void**)&ctxp, g_ctxp);
    cudaGetSymbolAddress((void**)&dynA, g_dynA);
    cudaGetSymbolAddress((void**)&dynB, g_dynB);
    cudaGetSymbolAddress((void**)&gictx, g_gictx);
    cudaGetSymbolAddress((void**)&wd0, g_wdyn0);
    cudaGetSymbolAddress((void**)&wdS, g_wdynS);
    cudaGetSymbolAddress((void**)&wpk, g_wpack);

    cudaFuncSetAttribute(gru_mma_kernel, cudaFuncAttributeMaxDynamicSharedMemorySize, GRU_SMEM);
    cudaFuncSetAttribute(proj_mma_kernel, cudaFuncAttributeMaxDynamicSharedMemorySize, PROJ_SMEM);

    // pack weights -> fp16 hi/lo (+ fp32 compact dyn slices)
    pack_kernel<<<768, 256>>>(Whh0, 768, 256, 0, 256, 256, O_WHH0, wpk);
    pack_kernel<<<768, 256>>>(Wih1, 768, 256, 0, 256, 256, O_WIH1, wpk);
    pack_kernel<<<768, 256>>>(Whh1, 768, 256, 0, 256, 256, O_WHH1, wpk);
    pack_kernel<<<768, 256>>>(Whhs, 768, 256, 0, 256, 256, O_WHHS, wpk);
    pack_kernel<<<384, 256>>>(Wihs, 768, 134, 0, 128, 128, O_WCTX, wpk);
    pack_kernel<<<128, 256>>>(P1, 128, 256, 0, 256, 256, O_PA, wpk);
    pack_kernel<<<64, 256>>>(A1, 64, 256, 0, 256, 256, O_PA + 128L * 256, wpk);
    wdyn_pack_kernel<<<24, 256>>>(Wih0, 6, 0, wd0);
    wdyn_pack_kernel<<<24, 256>>>(Wihs, 134, 128, wdS);

    zero_kernel<<<264, 256>>>(h0a, B * HDIM);
    zero_kernel<<<264, 256>>>(h1a, B * HDIM);
    prep_kernel<<<(B + 255) / 256, 256>>>(obs_traj, obs_Me, obsin, dynA, B, T);
    ctx_kernel<<<(B + 63) / 64, 256>>>(ctx, Cw, cb, ctxp, B);

    dim3 cgrid((B + 127) / 128, 8);

    // hoisted decoder ctx input-gates: gi_ctx = ctxp @ Wihs[:, :128].T
    gru_mma_kernel<<<cgrid, 256, GRU_SMEM>>>(ctxp, 128, 128, nullptr, 0,
                                             wpk, O_WCTX, 128, 0L,
                                             nullptr, nullptr, nullptr, 0,
                                             bihs, bhhs, nullptr, gictx, B, 1);

    // encoder
    float *h0i = h0a, *h0o = h0b, *h1i = h1a, *h1o = h1b;
    for (int t = 0; t < TS; t++) {
        gru_mma_kernel<<<cgrid, 256, GRU_SMEM>>>(nullptr, 0, 0,
                                                 h0i, (t > 0) ? 1 : 0,
                                                 wpk, 0L, 0, O_WHH0,
                                                 nullptr, wd0, obsin + (size_t)t * B * 6, 6,
                                                 bih0, bhh0, h0o, nullptr, B, 0);
        gru_mma_kernel<<<cgrid, 256, GRU_SMEM>>>(h0o, 256, 256,
                                                 h1i, (t > 0) ? 1 : 0,
                                                 wpk, O_WIH1, 256, O_WHH1,
                                                 nullptr, nullptr, nullptr, 0,
                                                 bih1, bhh1, h1o, nullptr, B, 0);
        float* t0 = h0i; h0i = h0o; h0o = t0;
        float* t1 = h1i; h1i = h1o; h1o = t1;
    }

    // decoder
    float* dhi = h1i;
    float* dho = h1o;
    float* dyi = dynA;
    float* dyo = dynB;
    for (int s = 0; s < PRED; s++) {
        gru_mma_kernel<<<cgrid, 256, GRU_SMEM>>>(nullptr, 0, 0,
                                                 dhi, 1,
                                                 wpk, 0L, 0, O_WHHS,
                                                 gictx, wdS, dyi, 6,
                                                 bihs, bhhs, dho, nullptr, B, 0);
        proj_mma_kernel<<<(B + 127) / 128, 256, PROJ_SMEM>>>(dho, wpk, p1b, a1b,
                                                             P2, p2b, A2, a2b,
                                                             out, dyo, B, s);
        float* td = dhi; dhi = dho; dho = td;
        float* ty_ = dyi; dyi = dyo; dyo = ty_;
    }
}

// round 15
// speedup vs baseline: 2.5713x; 1.1142x over previous
#include <cuda_runtime.h>
#include <cuda_fp16.h>
#include <math.h>
#include <stdint.h>

// ---------------------------------------------------------------------------
// DirectRegressionHead: 2-layer GRU encoder (7 steps) + 12-step GRU decoder.
// B=32768, H=256, CTX=128, PRED=12.
// fp16x2 weight-split mma.sync.m16n8k16 (A fp16, W = hi+lo fp16), fp32 acc.
// Activations keep an fp16 shadow in global; A and W staged via fully
// double-buffered cp.async (prefetched one K=64 chunk ahead).
// 256 thr, N=32 gate-cols, 95KB smem -> 2 CTAs/SM.
// ---------------------------------------------------------------------------

#define BMAX 32768
#define HDIM 256
#define CTXD 128
#define PRED 12
#define STR 72            // smem tile k-stride in halves (64 + 8 pad)
#define WHALF (96 * STR)  // halves between W hi and lo planes in one buffer

// packed weight layout (fp16 elements, hi plane; lo plane at +WTOT)
#define O_WHH0 0L
#define O_WIH1 196608L
#define O_WHH1 393216L
#define O_WHHS 589824L
#define O_WCTX 786432L     // 768 x 128 (Wihs cols 0..127)
#define O_PA   884736L     // 192 x 256 (P1 rows 0..127, A1 rows 128..191)
#define WTOT   933888L

// smem (bytes): A0 0 | A1 18432 | W0 36864 | W1 64512 | ext 92160
// gbuf (73728B) aliases A0+A1+W0+part of W1.
#define OFF_A1  18432
#define OFF_WB0 36864
#define OFF_WB1 64512
#define OFF_EXT 92160
#define GRU_SMEM 95232          // + wd_s 3072
#define PROJ_SMEM 192512        // + D1 100352

// --- static device scratch ---
__device__ float g_h0a[BMAX * HDIM];
__device__ float g_h0b[BMAX * HDIM];
__device__ float g_h1a[BMAX * HDIM];
__device__ float g_h1b[BMAX * HDIM];
__device__ __half g_h0a16[BMAX * HDIM];
__device__ __half g_h0b16[BMAX * HDIM];
__device__ __half g_h1a16[BMAX * HDIM];
__device__ __half g_h1b16[BMAX * HDIM];
__device__ __half g_ctxp16[BMAX * CTXD];
__device__ float g_obsin[8 * BMAX * 6];
__device__ float g_dynA[BMAX * 6];
__device__ float g_dynB[BMAX * 6];
__device__ float g_gictx[(size_t)BMAX * 768];
__device__ float g_wdyn0[768 * 8];
__device__ float g_wdynS[768 * 8];
__device__ __half g_wpack[2 * WTOT];

// ---------------- async-copy helpers ----------------
__device__ __forceinline__ void cp16(void* dst, const void* src) {
    uint32_t d = (uint32_t)__cvta_generic_to_shared(dst);
    asm volatile("cp.async.cg.shared.global [%0], [%1], 16;" :: "r"(d), "l"(src));
}
__device__ __forceinline__ void cp_commit() { asm volatile("cp.async.commit_group;"); }
__device__ __forceinline__ void cp_wait0() { asm volatile("cp.async.wait_group 0;"); }
__device__ __forceinline__ void cp_wait1() { asm volatile("cp.async.wait_group 1;"); }

// ---------------------------------------------------------------------------
__global__ void zero_kernel(float* __restrict__ p, int n) {
    int stride = gridDim.x * blockDim.x;
    for (int i = blockIdx.x * blockDim.x + threadIdx.x; i * 4 < n; i += stride)
        ((float4*)p)[i] = make_float4(0.f, 0.f, 0.f, 0.f);
}

// pack [rows, K] slice of src (row stride ld, col offset koff) -> hi/lo fp16
__global__ void pack_kernel(const float* __restrict__ W, int rows, int ld, int koff,
                            int K, int Kpad, long dst, __half* __restrict__ wp) {
    int i = blockIdx.x * blockDim.x + threadIdx.x;
    if (i >= rows * Kpad) return;
    int r = i / Kpad, k = i - r * Kpad;
    float v = (k < K) ? W[(size_t)r * ld + koff + k] : 0.f;
    __half h = __float2half(v);
    wp[dst + i] = h;
    wp[WTOT + dst + i] = __float2half(v - __half2float(h));
}

__global__ void wdyn_pack_kernel(const float* __restrict__ src, int ld, int koff,
                                 float* __restrict__ dst) {
    int i = blockIdx.x * blockDim.x + threadIdx.x;
    if (i >= 768 * 8) return;
    int r = i >> 3, q = i & 7;
    dst[i] = (q < 6) ? src[(size_t)r * ld + koff + q] : 0.f;
}

// ---------------------------------------------------------------------------
__global__ void prep_kernel(const float* __restrict__ traj,
                            const float* __restrict__ me,
                            float* __restrict__ obsin,
                            float* __restrict__ dyn, int B, int T) {
    int b = blockIdx.x * blockDim.x + threadIdx.x;
    if (b >= B) return;
    float vx[8], vy[8], mx[8], my_[8];
    int TS = T - 1;
    if (TS > 8) TS = 8;
    for (int t = 0; t < TS; t++) {
        vx[t]  = traj[((size_t)(t + 1) * B + b) * 2 + 0] - traj[((size_t)t * B + b) * 2 + 0];
        vy[t]  = traj[((size_t)(t + 1) * B + b) * 2 + 1] - traj[((size_t)t * B + b) * 2 + 1];
        mx[t]  = me[((size_t)(t + 1) * B + b) * 2 + 0] - me[((size_t)t * B + b) * 2 + 0];
        my_[t] = me[((size_t)(t + 1) * B + b) * 2 + 1] - me[((size_t)t * B + b) * 2 + 1];
    }
    for (int t = 0; t < TS; t++) {
        int ta = (t == 0) ? 1 : t;
        float ax = vx[ta] - vx[ta - 1];
        float ay = vy[ta] - vy[ta - 1];
        float* o = obsin + ((size_t)t * B + b) * 6;
        o[0] = vx[t]; o[1] = vy[t];
        o[2] = mx[t]; o[3] = my_[t];
        o[4] = ax;    o[5] = ay;
    }
    dyn[(size_t)b * 6 + 0] = vx[TS - 1];
    dyn[(size_t)b * 6 + 1] = vy[TS - 1];
    dyn[(size_t)b * 6 + 2] = vx[TS - 1] - vx[TS - 2];
    dyn[(size_t)b * 6 + 3] = vy[TS - 1] - vy[TS - 2];
    dyn[(size_t)b * 6 + 4] = mx[TS - 1];
    dyn[(size_t)b * 6 + 5] = my_[TS - 1];
}

// ---------------------------------------------------------------------------
// ctx projection -> fp16 activation (feeds only the hoisted ctx GEMM)
__global__ __launch_bounds__(256) void ctx_kernel(const float* __restrict__ ctx,
                                                  const float* __restrict__ Cw,
                                                  const float* __restrict__ cb,
                                                  __half* __restrict__ outp16, int B) {
    __shared__ float Cs[64][128];
    __shared__ float Wc[16][128];
    int tid = threadIdx.x;
    int m0 = blockIdx.x * 64;
    for (int i = tid; i < 64 * 128 / 4; i += 256) {
        int m = m0 + (i * 4) / 128;
        float4 v = make_float4(0.f, 0.f, 0.f, 0.f);
        if (m < B) v = *(const float4*)&ctx[(size_t)m0 * 128 + i * 4];
        ((float4*)Cs)[i] = v;
    }
    __syncthreads();
    int w = tid >> 5, lane = tid & 31;
    float acc[8][4];
#pragma unroll
    for (int i = 0; i < 8; i++)
#pragma unroll
        for (int u = 0; u < 4; u++) acc[i][u] = 0.f;

    for (int k0 = 0; k0 < 128; k0 += 16) {
        for (int i = tid; i < 16 * 128; i += 256) {
            int kk = i & 15, u = i >> 4;
            Wc[kk][u] = Cw[(size_t)u * 128 + k0 + kk];
        }
        __syncthreads();
#pragma unroll
        for (int kk = 0; kk < 16; kk++) {
            float wv[4];
#pragma unroll
            for (int u = 0; u < 4; u++) wv[u] = Wc[kk][lane * 4 + u];
#pragma unroll
            for (int i = 0; i < 8; i++) {
                float a = Cs[w * 8 + i][k0 + kk];
#pragma unroll
                for (int u = 0; u < 4; u++) acc[i][u] += a * wv[u];
            }
        }
        __syncthreads();
    }
#pragma unroll
    for (int i = 0; i < 8; i++) {
        int m = m0 + w * 8 + i;
        if (m >= B) continue;
#pragma unroll
        for (int u = 0; u < 4; u++) {
            int ug = lane * 4 + u;
            outp16[(size_t)m * 128 + ug] = __float2half(acc[i][u] + cb[ug]);
        }
    }
}

// ---------------------------------------------------------------------------
// tensor-core helpers (fp16)
// ---------------------------------------------------------------------------
__device__ __forceinline__ void mma_f16(float* c, const uint32_t* a, uint32_t b0, uint32_t b1) {
    asm volatile(
        "mma.sync.aligned.m16n8k16.row.col.f32.f16.f16.f32 "
        "{%0,%1,%2,%3}, {%4,%5,%6,%7}, {%8,%9}, {%0,%1,%2,%3};\n"
        : "+f"(c[0]), "+f"(c[1]), "+f"(c[2]), "+f"(c[3])
        : "r"(a[0]), "r"(a[1]), "r"(a[2]), "r"(a[3]), "r"(b0), "r"(b1));
}

__device__ __forceinline__ void ldsm_x4(uint32_t* r, const __half* base,
                                        int row, int col, int lane) {
    int g = lane >> 3, rr = lane & 7;
    const __half* p = base + (size_t)(row + (g & 1) * 8 + rr) * STR + col + (g >> 1) * 8;
    uint32_t addr = (uint32_t)__cvta_generic_to_shared(p);
    asm volatile("ldmatrix.sync.aligned.m8n8.x4.shared.b16 {%0,%1,%2,%3}, [%4];"
                 : "=r"(r[0]), "=r"(r[1]), "=r"(r[2]), "=r"(r[3]) : "r"(addr));
}

__device__ __forceinline__ void ldsm_x2(uint32_t* r, const __half* base,
                                        int row, int col, int lane) {
    int l = lane & 15;
    int g = l >> 3, rr = l & 7;
    const __half* p = base + (size_t)(row + rr) * STR + col + g * 8;
    uint32_t addr = (uint32_t)__cvta_generic_to_shared(p);
    asm volatile("ldmatrix.sync.aligned.m8n8.x2.shared.b16 {%0,%1}, [%2];"
                 : "=r"(r[0]), "=r"(r[1]) : "r"(addr));
}

template<bool ALT>
__device__ __forceinline__ void mma_all(float (&accA)[2][6][4], float (&accH)[2][2][4],
                                        uint32_t a[2][4], uint32_t b[6][2]) {
#pragma unroll
    for (int mf = 0; mf < 2; mf++)
#pragma unroll
        for (int f = 0; f < 6; f++) {
            float* c = (ALT && f >= 4) ? accH[mf][f - 4] : accA[mf][f];
            mma_f16(c, a[mf], b[f][0], b[f][1]);
        }
}

// acc += A16[128 x K] @ (Whi+Wlo)[96 x K]^T  (2 passes).
// A and W both staged via cp.async, double-buffered, one chunk ahead.
template<bool ALT>
__device__ __forceinline__ void gemm_phase(
    const __half* __restrict__ X16, int ldx, int K,
    const __half* __restrict__ wHi, const __half* __restrict__ wLo,
    int ldwp, int plane_stride,
    int m0, int n0,
    __half* Ab0, __half* Ab1, __half* Wb0, __half* Wb1,
    float (&accA)[2][6][4], float (&accH)[2][2][4]) {
    const int tid = threadIdx.x;
    const int lane = tid & 31;
    const int w = tid >> 5;
    const int mw = w >> 1;
    const int nw = w & 1;
    const int nch = K / 64;

    auto stageW = [&](__half* Wd, int kk) {
        for (int i = tid; i < 768; i += 256) {
            int r = i >> 3, q = i & 7;
            int grow = (r >> 5) * plane_stride + n0 + (r & 31);
            size_t so = (size_t)grow * ldwp + kk + q * 8;
            cp16(Wd + (size_t)r * STR + q * 8, wHi + so);
            cp16(Wd + WHALF + (size_t)r * STR + q * 8, wLo + so);
        }
    };
    auto stageA = [&](__half* Ad, int kk) {
        const __half* Xb = X16 + (size_t)m0 * ldx + kk;
        for (int i = tid; i < 1024; i += 256) {
            int r = i >> 3, q = i & 7;
            cp16(Ad + (size_t)r * STR + q * 8, Xb + (size_t)r * ldx + q * 8);
        }
    };

    stageA(Ab0, 0);
    stageW(Wb0, 0);
    cp_commit();

    for (int c = 0; c < nch; c++) {
        if (c + 1 < nch) {
            __half* Ad = (c & 1) ? Ab0 : Ab1;   // (c+1)&1
            __half* Wd = (c & 1) ? Wb0 : Wb1;
            stageA(Ad, (c + 1) * 64);
            stageW(Wd, (c + 1) * 64);
            cp_commit();
            cp_wait1();
        } else {
            cp_wait0();
        }
        __syncthreads();
        const __half* Ahi = (c & 1) ? Ab1 : Ab0;
        const __half* Whi = (c & 1) ? Wb1 : Wb0;
        const __half* Wlo2 = Whi + WHALF;
#pragma unroll
        for (int ks = 0; ks < 4; ks++) {
            uint32_t ah[2][4], b[6][2];
            ldsm_x4(ah[0], Ahi, mw * 32,      ks * 16, lane);
            ldsm_x4(ah[1], Ahi, mw * 32 + 16, ks * 16, lane);
#pragma unroll
            for (int f = 0; f < 6; f++) ldsm_x2(b[f], Whi, (f * 2 + nw) * 8, ks * 16, lane);
            mma_all<ALT>(accA, accH, ah, b);   // A * Whi
#pragma unroll
            for (int f = 0; f < 6; f++) ldsm_x2(b[f], Wlo2, (f * 2 + nw) * 8, ks * 16, lane);
            mma_all<ALT>(accA, accH, ah, b);   // A * Wlo
        }
        __syncthreads();
    }
}

// ---------------------------------------------------------------------------
// Fused GRU cell. mode 0: gate epilogue; mode 1: raw input-gates -> gi_out.
// ---------------------------------------------------------------------------
__global__ __launch_bounds__(256) void gru_mma_kernel(
    const __half* __restrict__ X1h, int ld1, int k1,
    const float* __restrict__ Hin, const __half* __restrict__ Hin16, int do_hidden,
    const __half* __restrict__ wpack,
    long wih_off, int wih_ldp, long whh_off,
    const float* __restrict__ gi_ext,
    const float* __restrict__ wdyn,
    const float* __restrict__ xdyn, int ld_dyn,
    const float* __restrict__ bih, const float* __restrict__ bhh,
    float* __restrict__ Hout, __half* __restrict__ Hout16,
    float* __restrict__ gi_out, int B, int mode) {
    extern __shared__ char sm_[];
    __half* Ab0 = (__half*)sm_;
    __half* Ab1 = (__half*)(sm_ + OFF_A1);
    __half* Wb0 = (__half*)(sm_ + OFF_WB0);
    __half* Wb1 = (__half*)(sm_ + OFF_WB1);
    float* gbuf = (float*)sm_;
    float* wd_s = (float*)(sm_ + OFF_EXT);

    const int tid = threadIdx.x;
    const int lane = tid & 31;
    const int w = tid >> 5;
    const int mw = w >> 1;
    const int nw = w & 1;
    const int m0 = blockIdx.x * 128;
    const int n0 = blockIdx.y * 32;

    if (wdyn != nullptr) {
        for (int i = tid; i < 768; i += 256) {
            int rr = i >> 3, q = i & 7;
            int p = rr >> 5, c = rr & 31;
            wd_s[i] = wdyn[((size_t)(p * 256) + n0 + c) * 8 + q];
        }
    }

    float accA[2][6][4];
    float accH[2][2][4];
#pragma unroll
    for (int mf = 0; mf < 2; mf++) {
#pragma unroll
        for (int f = 0; f < 6; f++)
#pragma unroll
            for (int u = 0; u < 4; u++) accA[mf][f][u] = 0.f;
#pragma unroll
        for (int f = 0; f < 2; f++)
#pragma unroll
            for (int u = 0; u < 4; u++) accH[mf][f][u] = 0.f;
    }

    if (X1h != nullptr)
        gemm_phase<false>(X1h, ld1, k1, wpack + wih_off, wpack + WTOT + wih_off,
                          wih_ldp, 256, m0, n0, Ab0, Ab1, Wb0, Wb1, accA, accH);
    if (do_hidden)
        gemm_phase<true>(Hin16, 256, 256, wpack + whh_off, wpack + WTOT + whh_off,
                         256, 256, m0, n0, Ab0, Ab1, Wb0, Wb1, accA, accH);

    // ---- scatter accumulators to gate buffer ----
    __syncthreads();
    {
        int r0 = mw * 32 + (lane >> 2);
        int cl = (lane & 3) * 2;
#pragma unroll
        for (int mf = 0; mf < 2; mf++) {
#pragma unroll
            for (int f = 0; f < 6; f++) {
                int gf = f * 2 + nw;
                int p = gf >> 2;
                int col = ((gf * 8) & 31) + cl;
                int rr = r0 + mf * 16;
                float* g0 = gbuf + ((size_t)(p * 128 + rr)) * 36 + col;
                g0[0] = accA[mf][f][0]; g0[1] = accA[mf][f][1];
                g0[8 * 36] = accA[mf][f][2]; g0[8 * 36 + 1] = accA[mf][f][3];
                if (f >= 4) {
                    float* g1 = gbuf + ((size_t)(3 * 128 + rr)) * 36 + col;
                    g1[0] = accH[mf][f - 4][0]; g1[1] = accH[mf][f - 4][1];
                    g1[8 * 36] = accH[mf][f - 4][2]; g1[8 * 36 + 1] = accH[mf][f - 4][3];
                }
            }
        }
    }
    __syncthreads();

    if (mode == 1) {
        for (int i = tid; i < 3 * 128 * 32; i += 256) {
            int p = i >> 12; int rem = i & 4095;
            int row = rem >> 5; int col = rem & 31;
            int m = m0 + row;
            if (m < B)
                gi_out[(size_t)m * 768 + p * 256 + n0 + col] =
                    gbuf[(size_t)(p * 128 + row) * 36 + col];
        }
        return;
    }

    // ---- gate epilogue ----
    {
        int row = tid >> 1;
        int m = m0 + row;
        int cbase = (tid & 1) * 16;
        bool valid = (m < B);
        float xd[6];
#pragma unroll
        for (int q = 0; q < 6; q++) xd[q] = 0.f;
        if (wdyn != nullptr && valid) {
#pragma unroll
            for (int q = 0; q < 6; q++) xd[q] = xdyn[(size_t)m * ld_dyn + q];
        }
        float ov[16];
#pragma unroll
        for (int c4 = 0; c4 < 4; c4++) {
            int col = cbase + c4 * 4;
            int jg = n0 + col;
            float grv[4], gzv[4], giv[4], ghv[4], hpv[4];
            *(float4*)grv = *(float4*)(gbuf + (size_t)(0 * 128 + row) * 36 + col);
            *(float4*)gzv = *(float4*)(gbuf + (size_t)(1 * 128 + row) * 36 + col);
            *(float4*)giv = *(float4*)(gbuf + (size_t)(2 * 128 + row) * 36 + col);
            *(float4*)ghv = *(float4*)(gbuf + (size_t)(3 * 128 + row) * 36 + col);
            if (valid) *(float4*)hpv = *(const float4*)(Hin + (size_t)m * 256 + jg);
            else { hpv[0] = hpv[1] = hpv[2] = hpv[3] = 0.f; }
            if (gi_ext != nullptr && valid) {
                float e0[4], e1[4], e2[4];
                *(float4*)e0 = *(const float4*)(gi_ext + (size_t)m * 768 + jg);
                *(float4*)e1 = *(const float4*)(gi_ext + (size_t)m * 768 + 256 + jg);
                *(float4*)e2 = *(const float4*)(gi_ext + (size_t)m * 768 + 512 + jg);
#pragma unroll
                for (int cc = 0; cc < 4; cc++) {
                    grv[cc] += e0[cc]; gzv[cc] += e1[cc]; giv[cc] += e2[cc];
                }
            }
            if (wdyn != nullptr) {
#pragma unroll
                for (int cc = 0; cc < 4; cc++) {
                    int cl_ = col + cc;
                    const float* w0 = wd_s + (0 * 32 + cl_) * 8;
                    const float* w1 = wd_s + (1 * 32 + cl_) * 8;
                    const float* w2 = wd_s + (2 * 32 + cl_) * 8;
#pragma unroll
                    for (int q = 0; q < 6; q++) {
                        grv[cc] += xd[q] * w0[q];
                        gzv[cc] += xd[q] * w1[q];
                        giv[cc] += xd[q] * w2[q];
                    }
                }
            }
#pragma unroll
            for (int cc = 0; cc < 4; cc++) {
                int j = jg + cc;
                float r_ = 1.f / (1.f + expf(-(grv[cc] + bih[j] + bhh[j])));
                float z_ = 1.f / (1.f + expf(-(gzv[cc] + bih[256 + j] + bhh[256 + j])));
                float n_ = tanhf(giv[cc] + bih[512 + j] + r_ * (ghv[cc] + bhh[512 + j]));
                ov[c4 * 4 + cc] = (1.f - z_) * n_ + z_ * hpv[cc];
            }
        }
        if (valid) {
#pragma unroll
            for (int c4 = 0; c4 < 4; c4++)
                *(float4*)(Hout + (size_t)m * 256 + n0 + cbase + c4 * 4) = *(float4*)(ov + c4 * 4);
            __half2 hh[8];
#pragma unroll
            for (int q = 0; q < 8; q++)
                hh[q] = __floats2half2_rn(ov[q * 2], ov[q * 2 + 1]);
            *(uint4*)(Hout16 + (size_t)m * 256 + n0 + cbase)     = *(uint4*)&hh[0];
            *(uint4*)(Hout16 + (size_t)m * 256 + n0 + cbase + 8) = *(uint4*)&hh[4];
        }
    }
}

// ---------------------------------------------------------------------------
// projection heads: stage1 [B,192] = GELU(H @ [P1;A1]^T + b), stage2 heads.
// ---------------------------------------------------------------------------
__device__ __forceinline__ void proj_scatter(float (&accA)[2][6][4], float* D1, int n0,
                                             const float* __restrict__ p1b,
                                             const float* __restrict__ a1b,
                                             int mw, int nw, int lane) {
    int r0 = mw * 32 + (lane >> 2);
    int cl = (lane & 3) * 2;
#pragma unroll
    for (int mf = 0; mf < 2; mf++)
#pragma unroll
        for (int f = 0; f < 6; f++) {
            int gf = f * 2 + nw;
            int colb = n0 + gf * 8 + cl;
            int rr = r0 + mf * 16;
#pragma unroll
            for (int jj = 0; jj < 2; jj++) {
                int col = colb + jj;
                float b = (col < 128) ? p1b[col] : a1b[col - 128];
                float v0 = accA[mf][f][jj] + b;
                float v1 = accA[mf][f][2 + jj] + b;
                D1[(size_t)rr * 196 + col] = v0 * normcdff(v0);
                D1[(size_t)(rr + 8) * 196 + col] = v1 * normcdff(v1);
            }
        }
}

__global__ __launch_bounds__(256) void proj_mma_kernel(
    const __half* __restrict__ H16,
    const __half* __restrict__ wpack,
    const float* __restrict__ p1b, const float* __restrict__ a1b,
    const float* __restrict__ P2, const float* __restrict__ p2b,
    const float* __restrict__ A2, const float* __restrict__ a2b,
    float* __restrict__ out, float* __restrict__ dyn, int B, int tstep) {
    extern __shared__ char sm_[];
    __half* Ab0 = (__half*)sm_;
    __half* Ab1 = (__half*)(sm_ + OFF_A1);
    __half* Wb0 = (__half*)(sm_ + OFF_WB0);
    __half* Wb1 = (__half*)(sm_ + OFF_WB1);
    float* D1 = (float*)(sm_ + OFF_EXT);
    float* wsm = (float*)sm_;   // reused after GEMM for head weights

    const int tid = threadIdx.x;
    const int lane = tid & 31;
    const int w = tid >> 5;
    const int mw = w >> 1;
    const int nw = w & 1;
    const int m0 = blockIdx.x * 128;

    float accA[2][6][4];
    float accH[2][2][4];
#pragma unroll
    for (int mf = 0; mf < 2; mf++) {
#pragma unroll
        for (int f = 0; f < 6; f++)
#pragma unroll
            for (int u = 0; u < 4; u++) accA[mf][f][u] = 0.f;
#pragma unroll
        for (int f = 0; f < 2; f++)
#pragma unroll
            for (int u = 0; u < 4; u++) accH[mf][f][u] = 0.f;
    }

    gemm_phase<false>(H16, 256, 256, wpack + O_PA, wpack + WTOT + O_PA,
                      256, 32, m0, 0, Ab0, Ab1, Wb0, Wb1, accA, accH);
    proj_scatter(accA, D1, 0, p1b, a1b, mw, nw, lane);
#pragma unroll
    for (int mf = 0; mf < 2; mf++)
#pragma unroll
        for (int f = 0; f < 6; f++)
#pragma unroll
            for (int u = 0; u < 4; u++) accA[mf][f][u] = 0.f;
    gemm_phase<false>(H16, 256, 256, wpack + O_PA, wpack + WTOT + O_PA,
                      256, 32, m0, 96, Ab0, Ab1, Wb0, Wb1, accA, accH);
    proj_scatter(accA, D1, 96, p1b, a1b, mw, nw, lane);
    __syncthreads();

    // stage head weights into (now free) tile smem
    for (int i = tid; i < 512; i += 256) wsm[i] = P2[i];
    if (tid < 128) wsm[512 + tid] = A2[tid];
    if (tid < 4) wsm[640 + tid] = p2b[tid];
    if (tid < 2) wsm[644 + tid] = a2b[tid];
    __syncthreads();

    // delta head: 128 rows x 4 outs, K=128
#pragma unroll
    for (int it = 0; it < 2; it++) {
        int idx = tid + it * 256;
        int s = idx >> 2, o = idx & 3;
        float a = wsm[640 + o];
        const float* w2 = wsm + o * 128;
        const float* d = D1 + (size_t)s * 196;
#pragma unroll 8
        for (int k = 0; k < 128; k++) a += d[k] * w2[k];
        int m = m0 + s;
        if (m < B) {
            out[(size_t)m * 48 + tstep * 4 + o] = a;
            dyn[(size_t)m * 6 + (o < 2 ? o : o + 2)] = a;
        }
    }
    // accel head: 128 rows x 2 outs, K=64
    {
        int s = tid >> 1, o = tid & 1;
        float a = wsm[644 + o];
        const float* w2 = wsm + 512 + o * 64;
        const float* d = D1 + (size_t)s * 196 + 128;
#pragma unroll 8
        for (int k = 0; k < 64; k++) a += d[k] * w2[k];
        int m = m0 + s;
        if (m < B) dyn[(size_t)m * 6 + 2 + o] = a;
    }
}

// ---------------------------------------------------------------------------
extern "C" void kernel_launch(void* const* d_in, const int* in_sizes, int n_in,
                              void* d_out, int out_size) {
    const float* ctx      = (const float*)d_in[0];
    const float* obs_traj = (const float*)d_in[1];
    const float* obs_Me   = (const float*)d_in[2];
    const float* Wih0 = (const float*)d_in[3];
    const float* Whh0 = (const float*)d_in[4];
    const float* bih0 = (const float*)d_in[5];
    const float* bhh0 = (const float*)d_in[6];
    const float* Wih1 = (const float*)d_in[7];
    const float* Whh1 = (const float*)d_in[8];
    const float* bih1 = (const float*)d_in[9];
    const float* bhh1 = (const float*)d_in[10];
    const float* Wihs = (const float*)d_in[11];
    const float* Whhs = (const float*)d_in[12];
    const float* bihs = (const float*)d_in[13];
    const float* bhhs = (const float*)d_in[14];
    const float* P1  = (const float*)d_in[15];
    const float* p1b = (const float*)d_in[16];
    const float* P2  = (const float*)d_in[17];
    const float* p2b = (const float*)d_in[18];
    const float* A1  = (const float*)d_in[19];
    const float* a1b = (const float*)d_in[20];
    const float* A2  = (const float*)d_in[21];
    const float* a2b = (const float*)d_in[22];
    const float* Cw  = (const float*)d_in[23];
    const float* cb  = (const float*)d_in[24];
    float* out = (float*)d_out;

    int B = in_sizes[0] / CTXD;
    if (B > BMAX) B = BMAX;
    int T = in_sizes[1] / (2 * B);
    int TS = T - 1;

    float *h0a, *h0b, *h1a, *h1b, *obsin, *dynA, *dynB, *gictx, *wd0, *wdS;
    __half *h0a16, *h0b16, *h1a16, *h1b16, *ctxp16, *wpk;
    cudaGetSymbolAddress((void**)&h0a, g_h0a);
    cudaGetSymbolAddress((void**)&h0b, g_h0b);
    cudaGetSymbolAddress((void**)&h1a, g_h1a);
    cudaGetSymbolAddress((void**)&h1b, g_h1b);
    cudaGetSymbolAddress((void**)&h0a16, g_h0a16);
    cudaGetSymbolAddress((void**)&h0b16, g_h0b16);
    cudaGetSymbolAddress((void**)&h1a16, g_h1a16);
    cudaGetSymbolAddress((void**)&h1b16, g_h1b16);
    cudaGetSymbolAddress((void**)&ctxp16, g_ctxp16);
    cudaGetSymbolAddress((void**)&obsin, g_obsin);
    cudaGetSymbolAddress((void**)&dynA, g_dynA);
    cudaGetSymbolAddress((void**)&dynB, g_dynB);
    cudaGetSymbolAddress((void**)&gictx, g_gictx);
    cudaGetSymbolAddress((void**)&wd0, g_wdyn0);
    cudaGetSymbolAddress((void**)&wdS, g_wdynS);
    cudaGetSymbolAddress((void**)&wpk, g_wpack);

    cudaFuncSetAttribute(gru_mma_kernel, cudaFuncAttributeMaxDynamicSharedMemorySize, GRU_SMEM);
    cudaFuncSetAttribute(proj_mma_kernel, cudaFuncAttributeMaxDynamicSharedMemorySize, PROJ_SMEM);

    pack_kernel<<<768, 256>>>(Whh0, 768, 256, 0, 256, 256, O_WHH0, wpk);
    pack_kernel<<<768, 256>>>(Wih1, 768, 256, 0, 256, 256, O_WIH1, wpk);
    pack_kernel<<<768, 256>>>(Whh1, 768, 256, 0, 256, 256, O_WHH1, wpk);
    pack_kernel<<<768, 256>>>(Whhs, 768, 256, 0, 256, 256, O_WHHS, wpk);
    pack_kernel<<<384, 256>>>(Wihs, 768, 134, 0, 128, 128, O_WCTX, wpk);
    pack_kernel<<<128, 256>>>(P1, 128, 256, 0, 256, 256, O_PA, wpk);
    pack_kernel<<<64, 256>>>(A1, 64, 256, 0, 256, 256, O_PA + 128L * 256, wpk);
    wdyn_pack_kernel<<<24, 256>>>(Wih0, 6, 0, wd0);
    wdyn_pack_kernel<<<24, 256>>>(Wihs, 134, 128, wdS);

    zero_kernel<<<264, 256>>>(h0a, B * HDIM);
    zero_kernel<<<264, 256>>>(h1a, B * HDIM);
    prep_kernel<<<(B + 255) / 256, 256>>>(obs_traj, obs_Me, obsin, dynA, B, T);
    ctx_kernel<<<(B + 63) / 64, 256>>>(ctx, Cw, cb, ctxp16, B);

    dim3 cgrid((B + 127) / 128, 8);

    // hoisted decoder ctx input-gates: gi_ctx = ctxp @ Wihs[:, :128].T
    gru_mma_kernel<<<cgrid, 256, GRU_SMEM>>>(ctxp16, 128, 128,
                                             h1a, nullptr, 0,
                                             wpk, O_WCTX, 128, 0L,
                                             nullptr, nullptr, nullptr, 0,
                                             bihs, bhhs, nullptr, nullptr, gictx, B, 1);

    // encoder
    float *h0i = h0a, *h0o = h0b, *h1i = h1a, *h1o = h1b;
    __half *h0i16 = h0a16, *h0o16 = h0b16, *h1i16 = h1a16, *h1o16 = h1b16;
    for (int t = 0; t < TS; t++) {
        gru_mma_kernel<<<cgrid, 256, GRU_SMEM>>>(nullptr, 0, 0,
                                                 h0i, h0i16, (t > 0) ? 1 : 0,
                                                 wpk, 0L, 0, O_WHH0,
                                                 nullptr, wd0, obsin + (size_t)t * B * 6, 6,
                                                 bih0, bhh0, h0o, h0o16, nullptr, B, 0);
        gru_mma_kernel<<<cgrid, 256, GRU_SMEM>>>(h0o16, 256, 256,
                                                 h1i, h1i16, (t > 0) ? 1 : 0,
                                                 wpk, O_WIH1, 256, O_WHH1,
                                                 nullptr, nullptr, nullptr, 0,
                                                 bih1, bhh1, h1o, h1o16, nullptr, B, 0);
        float* t0 = h0i; h0i = h0o; h0o = t0;
        float* t1 = h1i; h1i = h1o; h1o = t1;
        __half* s0 = h0i16; h0i16 = h0o16; h0o16 = s0;
        __half* s1 = h1i16; h1i16 = h1o16; h1o16 = s1;
    }

    // decoder
    float* dhi = h1i;
    float* dho = h1o;
    __half* dhi16 = h1i16;
    __half* dho16 = h1o16;
    float* dyi = dynA;
    float* dyo = dynB;
    for (int s = 0; s < PRED; s++) {
        gru_mma_kernel<<<cgrid, 256, GRU_SMEM>>>(nullptr, 0, 0,
                                                 dhi, dhi16, 1,
                                                 wpk, 0L, 0, O_WHHS,
                                                 gictx, wdS, dyi, 6,
                                                 bihs, bhhs, dho, dho16, nullptr, B, 0);
        proj_mma_kernel<<<(B + 127) / 128, 256, PROJ_SMEM>>>(dho16, wpk, p1b, a1b,
                                                             P2, p2b, A2, a2b,
                                                             out, dyo, B, s);
        float* td = dhi; dhi = dho; dho = td;
        __half* ts = dhi16; dhi16 = dho16; dho16 = ts;
        float* ty_ = dyi; dyi = dyo; dyo = ty_;
    }
}

// round 16
// speedup vs baseline: 3.1453x; 1.2232x over previous
#include <cuda_runtime.h>
#include <cuda_fp16.h>
#include <math.h>
#include <stdint.h>

// ---------------------------------------------------------------------------
// DirectRegressionHead: 2-layer GRU encoder (7 steps) + 12-step GRU decoder.
// B=32768, H=256, CTX=128, PRED=12.
// Single-pass fp16 mma.sync.m16n8k16 (A fp16, W fp16), fp32 accumulate.
// Activations keep an fp16 shadow in global; A and W staged via fully
// double-buffered cp.async (prefetched one K=64 chunk ahead).
// 256 thr, N=32 gate-cols, 76.8KB smem -> 2 CTAs/SM.
// ---------------------------------------------------------------------------

#define BMAX 32768
#define HDIM 256
#define CTXD 128
#define PRED 12
#define STR 72            // smem tile k-stride in halves (64 + 8 pad)

// packed weight layout (fp16 elements)
#define O_WHH0 0L
#define O_WIH1 196608L
#define O_WHH1 393216L
#define O_WHHS 589824L
#define O_WCTX 786432L     // 768 x 128 (Wihs cols 0..127)
#define O_PA   884736L     // 192 x 256 (P1 rows 0..127, A1 rows 128..191)
#define WTOT   933888L

// smem (bytes): A0 0 | A1 18432 | W0 36864 | W1 50688 | (gap) | ext 73728
// gbuf (73728B) aliases A0..W1+gap.
#define OFF_A1  18432
#define OFF_WB0 36864
#define OFF_WB1 50688
#define OFF_EXT 73728
#define GRU_SMEM 76800          // gbuf 73728 + wd_s 3072
#define PROJ_SMEM 174080        // 73728 + D1 100352

// --- static device scratch ---
__device__ float g_h0a[BMAX * HDIM];
__device__ float g_h0b[BMAX * HDIM];
__device__ float g_h1a[BMAX * HDIM];
__device__ float g_h1b[BMAX * HDIM];
__device__ __half g_h0a16[BMAX * HDIM];
__device__ __half g_h0b16[BMAX * HDIM];
__device__ __half g_h1a16[BMAX * HDIM];
__device__ __half g_h1b16[BMAX * HDIM];
__device__ __half g_ctxp16[BMAX * CTXD];
__device__ float g_obsin[8 * BMAX * 6];
__device__ float g_dynA[BMAX * 6];
__device__ float g_dynB[BMAX * 6];
__device__ float g_gictx[(size_t)BMAX * 768];
__device__ float g_wdyn0[768 * 8];
__device__ float g_wdynS[768 * 8];
__device__ __half g_wpack[WTOT];

// ---------------- async-copy helpers ----------------
__device__ __forceinline__ void cp16(void* dst, const void* src) {
    uint32_t d = (uint32_t)__cvta_generic_to_shared(dst);
    asm volatile("cp.async.cg.shared.global [%0], [%1], 16;" :: "r"(d), "l"(src));
}
__device__ __forceinline__ void cp_commit() { asm volatile("cp.async.commit_group;"); }
__device__ __forceinline__ void cp_wait0() { asm volatile("cp.async.wait_group 0;"); }
__device__ __forceinline__ void cp_wait1() { asm volatile("cp.async.wait_group 1;"); }

// ---------------------------------------------------------------------------
__global__ void zero_kernel(float* __restrict__ p, int n) {
    int stride = gridDim.x * blockDim.x;
    for (int i = blockIdx.x * blockDim.x + threadIdx.x; i * 4 < n; i += stride)
        ((float4*)p)[i] = make_float4(0.f, 0.f, 0.f, 0.f);
}

// pack [rows, K] slice of src (row stride ld, col offset koff) -> fp16
__global__ void pack_kernel(const float* __restrict__ W, int rows, int ld, int koff,
                            int K, int Kpad, long dst, __half* __restrict__ wp) {
    int i = blockIdx.x * blockDim.x + threadIdx.x;
    if (i >= rows * Kpad) return;
    int r = i / Kpad, k = i - r * Kpad;
    float v = (k < K) ? W[(size_t)r * ld + koff + k] : 0.f;
    wp[dst + i] = __float2half(v);
}

__global__ void wdyn_pack_kernel(const float* __restrict__ src, int ld, int koff,
                                 float* __restrict__ dst) {
    int i = blockIdx.x * blockDim.x + threadIdx.x;
    if (i >= 768 * 8) return;
    int r = i >> 3, q = i & 7;
    dst[i] = (q < 6) ? src[(size_t)r * ld + koff + q] : 0.f;
}

// ---------------------------------------------------------------------------
__global__ void prep_kernel(const float* __restrict__ traj,
                            const float* __restrict__ me,
                            float* __restrict__ obsin,
                            float* __restrict__ dyn, int B, int T) {
    int b = blockIdx.x * blockDim.x + threadIdx.x;
    if (b >= B) return;
    float vx[8], vy[8], mx[8], my_[8];
    int TS = T - 1;
    if (TS > 8) TS = 8;
    for (int t = 0; t < TS; t++) {
        vx[t]  = traj[((size_t)(t + 1) * B + b) * 2 + 0] - traj[((size_t)t * B + b) * 2 + 0];
        vy[t]  = traj[((size_t)(t + 1) * B + b) * 2 + 1] - traj[((size_t)t * B + b) * 2 + 1];
        mx[t]  = me[((size_t)(t + 1) * B + b) * 2 + 0] - me[((size_t)t * B + b) * 2 + 0];
        my_[t] = me[((size_t)(t + 1) * B + b) * 2 + 1] - me[((size_t)t * B + b) * 2 + 1];
    }
    for (int t = 0; t < TS; t++) {
        int ta = (t == 0) ? 1 : t;
        float ax = vx[ta] - vx[ta - 1];
        float ay = vy[ta] - vy[ta - 1];
        float* o = obsin + ((size_t)t * B + b) * 6;
        o[0] = vx[t]; o[1] = vy[t];
        o[2] = mx[t]; o[3] = my_[t];
        o[4] = ax;    o[5] = ay;
    }
    dyn[(size_t)b * 6 + 0] = vx[TS - 1];
    dyn[(size_t)b * 6 + 1] = vy[TS - 1];
    dyn[(size_t)b * 6 + 2] = vx[TS - 1] - vx[TS - 2];
    dyn[(size_t)b * 6 + 3] = vy[TS - 1] - vy[TS - 2];
    dyn[(size_t)b * 6 + 4] = mx[TS - 1];
    dyn[(size_t)b * 6 + 5] = my_[TS - 1];
}

// ---------------------------------------------------------------------------
// ctx projection -> fp16 activation (feeds only the hoisted ctx GEMM)
__global__ __launch_bounds__(256) void ctx_kernel(const float* __restrict__ ctx,
                                                  const float* __restrict__ Cw,
                                                  const float* __restrict__ cb,
                                                  __half* __restrict__ outp16, int B) {
    __shared__ float Cs[64][128];
    __shared__ float Wc[16][128];
    int tid = threadIdx.x;
    int m0 = blockIdx.x * 64;
    for (int i = tid; i < 64 * 128 / 4; i += 256) {
        int m = m0 + (i * 4) / 128;
        float4 v = make_float4(0.f, 0.f, 0.f, 0.f);
        if (m < B) v = *(const float4*)&ctx[(size_t)m0 * 128 + i * 4];
        ((float4*)Cs)[i] = v;
    }
    __syncthreads();
    int w = tid >> 5, lane = tid & 31;
    float acc[8][4];
#pragma unroll
    for (int i = 0; i < 8; i++)
#pragma unroll
        for (int u = 0; u < 4; u++) acc[i][u] = 0.f;

    for (int k0 = 0; k0 < 128; k0 += 16) {
        for (int i = tid; i < 16 * 128; i += 256) {
            int kk = i & 15, u = i >> 4;
            Wc[kk][u] = Cw[(size_t)u * 128 + k0 + kk];
        }
        __syncthreads();
#pragma unroll
        for (int kk = 0; kk < 16; kk++) {
            float wv[4];
#pragma unroll
            for (int u = 0; u < 4; u++) wv[u] = Wc[kk][lane * 4 + u];
#pragma unroll
            for (int i = 0; i < 8; i++) {
                float a = Cs[w * 8 + i][k0 + kk];
#pragma unroll
                for (int u = 0; u < 4; u++) acc[i][u] += a * wv[u];
            }
        }
        __syncthreads();
    }
#pragma unroll
    for (int i = 0; i < 8; i++) {
        int m = m0 + w * 8 + i;
        if (m >= B) continue;
#pragma unroll
        for (int u = 0; u < 4; u++) {
            int ug = lane * 4 + u;
            outp16[(size_t)m * 128 + ug] = __float2half(acc[i][u] + cb[ug]);
        }
    }
}

// ---------------------------------------------------------------------------
// tensor-core helpers (fp16)
// ---------------------------------------------------------------------------
__device__ __forceinline__ void mma_f16(float* c, const uint32_t* a, uint32_t b0, uint32_t b1) {
    asm volatile(
        "mma.sync.aligned.m16n8k16.row.col.f32.f16.f16.f32 "
        "{%0,%1,%2,%3}, {%4,%5,%6,%7}, {%8,%9}, {%0,%1,%2,%3};\n"
        : "+f"(c[0]), "+f"(c[1]), "+f"(c[2]), "+f"(c[3])
        : "r"(a[0]), "r"(a[1]), "r"(a[2]), "r"(a[3]), "r"(b0), "r"(b1));
}

__device__ __forceinline__ void ldsm_x4(uint32_t* r, const __half* base,
                                        int row, int col, int lane) {
    int g = lane >> 3, rr = lane & 7;
    const __half* p = base + (size_t)(row + (g & 1) * 8 + rr) * STR + col + (g >> 1) * 8;
    uint32_t addr = (uint32_t)__cvta_generic_to_shared(p);
    asm volatile("ldmatrix.sync.aligned.m8n8.x4.shared.b16 {%0,%1,%2,%3}, [%4];"
                 : "=r"(r[0]), "=r"(r[1]), "=r"(r[2]), "=r"(r[3]) : "r"(addr));
}

__device__ __forceinline__ void ldsm_x2(uint32_t* r, const __half* base,
                                        int row, int col, int lane) {
    int l = lane & 15;
    int g = l >> 3, rr = l & 7;
    const __half* p = base + (size_t)(row + rr) * STR + col + g * 8;
    uint32_t addr = (uint32_t)__cvta_generic_to_shared(p);
    asm volatile("ldmatrix.sync.aligned.m8n8.x2.shared.b16 {%0,%1}, [%2];"
                 : "=r"(r[0]), "=r"(r[1]) : "r"(addr));
}

template<bool ALT>
__device__ __forceinline__ void mma_all(float (&accA)[2][6][4], float (&accH)[2][2][4],
                                        uint32_t a[2][4], uint32_t b[6][2]) {
#pragma unroll
    for (int mf = 0; mf < 2; mf++)
#pragma unroll
        for (int f = 0; f < 6; f++) {
            float* c = (ALT && f >= 4) ? accH[mf][f - 4] : accA[mf][f];
            mma_f16(c, a[mf], b[f][0], b[f][1]);
        }
}

// acc += A16[128 x K] @ W16[96 x K]^T  (single pass).
// A and W both staged via cp.async, double-buffered, one chunk ahead.
template<bool ALT>
__device__ __forceinline__ void gemm_phase(
    const __half* __restrict__ X16, int ldx, int K,
    const __half* __restrict__ wHi,
    int ldwp, int plane_stride,
    int m0, int n0,
    __half* Ab0, __half* Ab1, __half* Wb0, __half* Wb1,
    float (&accA)[2][6][4], float (&accH)[2][2][4]) {
    const int tid = threadIdx.x;
    const int lane = tid & 31;
    const int w = tid >> 5;
    const int mw = w >> 1;
    const int nw = w & 1;
    const int nch = K / 64;

    auto stageW = [&](__half* Wd, int kk) {
        for (int i = tid; i < 768; i += 256) {
            int r = i >> 3, q = i & 7;
            int grow = (r >> 5) * plane_stride + n0 + (r & 31);
            size_t so = (size_t)grow * ldwp + kk + q * 8;
            cp16(Wd + (size_t)r * STR + q * 8, wHi + so);
        }
    };
    auto stageA = [&](__half* Ad, int kk) {
        const __half* Xb = X16 + (size_t)m0 * ldx + kk;
        for (int i = tid; i < 1024; i += 256) {
            int r = i >> 3, q = i & 7;
            cp16(Ad + (size_t)r * STR + q * 8, Xb + (size_t)r * ldx + q * 8);
        }
    };

    stageA(Ab0, 0);
    stageW(Wb0, 0);
    cp_commit();

    for (int c = 0; c < nch; c++) {
        if (c + 1 < nch) {
            __half* Ad = (c & 1) ? Ab0 : Ab1;   // (c+1)&1
            __half* Wd = (c & 1) ? Wb0 : Wb1;
            stageA(Ad, (c + 1) * 64);
            stageW(Wd, (c + 1) * 64);
            cp_commit();
            cp_wait1();
        } else {
            cp_wait0();
        }
        __syncthreads();
        const __half* Ahi = (c & 1) ? Ab1 : Ab0;
        const __half* Whi = (c & 1) ? Wb1 : Wb0;
#pragma unroll
        for (int ks = 0; ks < 4; ks++) {
            uint32_t ah[2][4], b[6][2];
            ldsm_x4(ah[0], Ahi, mw * 32,      ks * 16, lane);
            ldsm_x4(ah[1], Ahi, mw * 32 + 16, ks * 16, lane);
#pragma unroll
            for (int f = 0; f < 6; f++) ldsm_x2(b[f], Whi, (f * 2 + nw) * 8, ks * 16, lane);
            mma_all<ALT>(accA, accH, ah, b);
        }
        __syncthreads();
    }
}

// ---------------------------------------------------------------------------
// Fused GRU cell. mode 0: gate epilogue; mode 1: raw input-gates -> gi_out.
// ---------------------------------------------------------------------------
__global__ __launch_bounds__(256) void gru_mma_kernel(
    const __half* __restrict__ X1h, int ld1, int k1,
    const float* __restrict__ Hin, const __half* __restrict__ Hin16, int do_hidden,
    const __half* __restrict__ wpack,
    long wih_off, int wih_ldp, long whh_off,
    const float* __restrict__ gi_ext,
    const float* __restrict__ wdyn,
    const float* __restrict__ xdyn, int ld_dyn,
    const float* __restrict__ bih, const float* __restrict__ bhh,
    float* __restrict__ Hout, __half* __restrict__ Hout16,
    float* __restrict__ gi_out, int B, int mode) {
    extern __shared__ char sm_[];
    __half* Ab0 = (__half*)sm_;
    __half* Ab1 = (__half*)(sm_ + OFF_A1);
    __half* Wb0 = (__half*)(sm_ + OFF_WB0);
    __half* Wb1 = (__half*)(sm_ + OFF_WB1);
    float* gbuf = (float*)sm_;
    float* wd_s = (float*)(sm_ + OFF_EXT);

    const int tid = threadIdx.x;
    const int lane = tid & 31;
    const int w = tid >> 5;
    const int mw = w >> 1;
    const int nw = w & 1;
    const int m0 = blockIdx.x * 128;
    const int n0 = blockIdx.y * 32;

    if (wdyn != nullptr) {
        for (int i = tid; i < 768; i += 256) {
            int rr = i >> 3, q = i & 7;
            int p = rr >> 5, c = rr & 31;
            wd_s[i] = wdyn[((size_t)(p * 256) + n0 + c) * 8 + q];
        }
    }

    float accA[2][6][4];
    float accH[2][2][4];
#pragma unroll
    for (int mf = 0; mf < 2; mf++) {
#pragma unroll
        for (int f = 0; f < 6; f++)
#pragma unroll
            for (int u = 0; u < 4; u++) accA[mf][f][u] = 0.f;
#pragma unroll
        for (int f = 0; f < 2; f++)
#pragma unroll
            for (int u = 0; u < 4; u++) accH[mf][f][u] = 0.f;
    }

    if (X1h != nullptr)
        gemm_phase<false>(X1h, ld1, k1, wpack + wih_off,
                          wih_ldp, 256, m0, n0, Ab0, Ab1, Wb0, Wb1, accA, accH);
    if (do_hidden)
        gemm_phase<true>(Hin16, 256, 256, wpack + whh_off,
                         256, 256, m0, n0, Ab0, Ab1, Wb0, Wb1, accA, accH);

    // ---- scatter accumulators to gate buffer ----
    __syncthreads();
    {
        int r0 = mw * 32 + (lane >> 2);
        int cl = (lane & 3) * 2;
#pragma unroll
        for (int mf = 0; mf < 2; mf++) {
#pragma unroll
            for (int f = 0; f < 6; f++) {
                int gf = f * 2 + nw;
                int p = gf >> 2;
                int col = ((gf * 8) & 31) + cl;
                int rr = r0 + mf * 16;
                float* g0 = gbuf + ((size_t)(p * 128 + rr)) * 36 + col;
                g0[0] = accA[mf][f][0]; g0[1] = accA[mf][f][1];
                g0[8 * 36] = accA[mf][f][2]; g0[8 * 36 + 1] = accA[mf][f][3];
                if (f >= 4) {
                    float* g1 = gbuf + ((size_t)(3 * 128 + rr)) * 36 + col;
                    g1[0] = accH[mf][f - 4][0]; g1[1] = accH[mf][f - 4][1];
                    g1[8 * 36] = accH[mf][f - 4][2]; g1[8 * 36 + 1] = accH[mf][f - 4][3];
                }
            }
        }
    }
    __syncthreads();

    if (mode == 1) {
        for (int i = tid; i < 3 * 128 * 32; i += 256) {
            int p = i >> 12; int rem = i & 4095;
            int row = rem >> 5; int col = rem & 31;
            int m = m0 + row;
            if (m < B)
                gi_out[(size_t)m * 768 + p * 256 + n0 + col] =
                    gbuf[(size_t)(p * 128 + row) * 36 + col];
        }
        return;
    }

    // ---- gate epilogue ----
    {
        int row = tid >> 1;
        int m = m0 + row;
        int cbase = (tid & 1) * 16;
        bool valid = (m < B);
        float xd[6];
#pragma unroll
        for (int q = 0; q < 6; q++) xd[q] = 0.f;
        if (wdyn != nullptr && valid) {
#pragma unroll
            for (int q = 0; q < 6; q++) xd[q] = xdyn[(size_t)m * ld_dyn + q];
        }
        float ov[16];
#pragma unroll
        for (int c4 = 0; c4 < 4; c4++) {
            int col = cbase + c4 * 4;
            int jg = n0 + col;
            float grv[4], gzv[4], giv[4], ghv[4], hpv[4];
            *(float4*)grv = *(float4*)(gbuf + (size_t)(0 * 128 + row) * 36 + col);
            *(float4*)gzv = *(float4*)(gbuf + (size_t)(1 * 128 + row) * 36 + col);
            *(float4*)giv = *(float4*)(gbuf + (size_t)(2 * 128 + row) * 36 + col);
            *(float4*)ghv = *(float4*)(gbuf + (size_t)(3 * 128 + row) * 36 + col);
            if (valid) *(float4*)hpv = *(const float4*)(Hin + (size_t)m * 256 + jg);
            else { hpv[0] = hpv[1] = hpv[2] = hpv[3] = 0.f; }
            if (gi_ext != nullptr && valid) {
                float e0[4], e1[4], e2[4];
                *(float4*)e0 = *(const float4*)(gi_ext + (size_t)m * 768 + jg);
                *(float4*)e1 = *(const float4*)(gi_ext + (size_t)m * 768 + 256 + jg);
                *(float4*)e2 = *(const float4*)(gi_ext + (size_t)m * 768 + 512 + jg);
#pragma unroll
                for (int cc = 0; cc < 4; cc++) {
                    grv[cc] += e0[cc]; gzv[cc] += e1[cc]; giv[cc] += e2[cc];
                }
            }
            if (wdyn != nullptr) {
#pragma unroll
                for (int cc = 0; cc < 4; cc++) {
                    int cl_ = col + cc;
                    const float* w0 = wd_s + (0 * 32 + cl_) * 8;
                    const float* w1 = wd_s + (1 * 32 + cl_) * 8;
                    const float* w2 = wd_s + (2 * 32 + cl_) * 8;
#pragma unroll
                    for (int q = 0; q < 6; q++) {
                        grv[cc] += xd[q] * w0[q];
                        gzv[cc] += xd[q] * w1[q];
                        giv[cc] += xd[q] * w2[q];
                    }
                }
            }
#pragma unroll
            for (int cc = 0; cc < 4; cc++) {
                int j = jg + cc;
                float r_ = 1.f / (1.f + expf(-(grv[cc] + bih[j] + bhh[j])));
                float z_ = 1.f / (1.f + expf(-(gzv[cc] + bih[256 + j] + bhh[256 + j])));
                float n_ = tanhf(giv[cc] + bih[512 + j] + r_ * (ghv[cc] + bhh[512 + j]));
                ov[c4 * 4 + cc] = (1.f - z_) * n_ + z_ * hpv[cc];
            }
        }
        if (valid) {
#pragma unroll
            for (int c4 = 0; c4 < 4; c4++)
                *(float4*)(Hout + (size_t)m * 256 + n0 + cbase + c4 * 4) = *(float4*)(ov + c4 * 4);
            __half2 hh[8];
#pragma unroll
            for (int q = 0; q < 8; q++)
                hh[q] = __floats2half2_rn(ov[q * 2], ov[q * 2 + 1]);
            *(uint4*)(Hout16 + (size_t)m * 256 + n0 + cbase)     = *(uint4*)&hh[0];
            *(uint4*)(Hout16 + (size_t)m * 256 + n0 + cbase + 8) = *(uint4*)&hh[4];
        }
    }
}

// ---------------------------------------------------------------------------
// projection heads: stage1 [B,192] = GELU(H @ [P1;A1]^T + b), stage2 heads.
// ---------------------------------------------------------------------------
__device__ __forceinline__ void proj_scatter(float (&accA)[2][6][4], float* D1, int n0,
                                             const float* __restrict__ p1b,
                                             const float* __restrict__ a1b,
                                             int mw, int nw, int lane) {
    int r0 = mw * 32 + (lane >> 2);
    int cl = (lane & 3) * 2;
#pragma unroll
    for (int mf = 0; mf < 2; mf++)
#pragma unroll
        for (int f = 0; f < 6; f++) {
            int gf = f * 2 + nw;
            int colb = n0 + gf * 8 + cl;
            int rr = r0 + mf * 16;
#pragma unroll
            for (int jj = 0; jj < 2; jj++) {
                int col = colb + jj;
                float b = (col < 128) ? p1b[col] : a1b[col - 128];
                float v0 = accA[mf][f][jj] + b;
                float v1 = accA[mf][f][2 + jj] + b;
                D1[(size_t)rr * 196 + col] = v0 * normcdff(v0);
                D1[(size_t)(rr + 8) * 196 + col] = v1 * normcdff(v1);
            }
        }
}

__global__ __launch_bounds__(256) void proj_mma_kernel(
    const __half* __restrict__ H16,
    const __half* __restrict__ wpack,
    const float* __restrict__ p1b, const float* __restrict__ a1b,
    const float* __restrict__ P2, const float* __restrict__ p2b,
    const float* __restrict__ A2, const float* __restrict__ a2b,
    float* __restrict__ out, float* __restrict__ dyn, int B, int tstep) {
    extern __shared__ char sm_[];
    __half* Ab0 = (__half*)sm_;
    __half* Ab1 = (__half*)(sm_ + OFF_A1);
    __half* Wb0 = (__half*)(sm_ + OFF_WB0);
    __half* Wb1 = (__half*)(sm_ + OFF_WB1);
    float* D1 = (float*)(sm_ + OFF_EXT);
    float* wsm = (float*)sm_;   // reused after GEMM for head weights

    const int tid = threadIdx.x;
    const int lane = tid & 31;
    const int w = tid >> 5;
    const int mw = w >> 1;
    const int nw = w & 1;
    const int m0 = blockIdx.x * 128;

    float accA[2][6][4];
    float accH[2][2][4];
#pragma unroll
    for (int mf = 0; mf < 2; mf++) {
#pragma unroll
        for (int f = 0; f < 6; f++)
#pragma unroll
            for (int u = 0; u < 4; u++) accA[mf][f][u] = 0.f;
#pragma unroll
        for (int f = 0; f < 2; f++)
#pragma unroll
            for (int u = 0; u < 4; u++) accH[mf][f][u] = 0.f;
    }

    gemm_phase<false>(H16, 256, 256, wpack + O_PA,
                      256, 32, m0, 0, Ab0, Ab1, Wb0, Wb1, accA, accH);
    proj_scatter(accA, D1, 0, p1b, a1b, mw, nw, lane);
#pragma unroll
    for (int mf = 0; mf < 2; mf++)
#pragma unroll
        for (int f = 0; f < 6; f++)
#pragma unroll
            for (int u = 0; u < 4; u++) accA[mf][f][u] = 0.f;
    gemm_phase<false>(H16, 256, 256, wpack + O_PA,
                      256, 32, m0, 96, Ab0, Ab1, Wb0, Wb1, accA, accH);
    proj_scatter(accA, D1, 96, p1b, a1b, mw, nw, lane);
    __syncthreads();

    // stage head weights into (now free) tile smem
    for (int i = tid; i < 512; i += 256) wsm[i] = P2[i];
    if (tid < 128) wsm[512 + tid] = A2[tid];
    if (tid < 4) wsm[640 + tid] = p2b[tid];
    if (tid < 2) wsm[644 + tid] = a2b[tid];
    __syncthreads();

    // delta head: 128 rows x 4 outs, K=128
#pragma unroll
    for (int it = 0; it < 2; it++) {
        int idx = tid + it * 256;
        int s = idx >> 2, o = idx & 3;
        float a = wsm[640 + o];
        const float* w2 = wsm + o * 128;
        const float* d = D1 + (size_t)s * 196;
#pragma unroll 8
        for (int k = 0; k < 128; k++) a += d[k] * w2[k];
        int m = m0 + s;
        if (m < B) {
            out[(size_t)m * 48 + tstep * 4 + o] = a;
            dyn[(size_t)m * 6 + (o < 2 ? o : o + 2)] = a;
        }
    }
    // accel head: 128 rows x 2 outs, K=64
    {
        int s = tid >> 1, o = tid & 1;
        float a = wsm[644 + o];
        const float* w2 = wsm + 512 + o * 64;
        const float* d = D1 + (size_t)s * 196 + 128;
#pragma unroll 8
        for (int k = 0; k < 64; k++) a += d[k] * w2[k];
        int m = m0 + s;
        if (m < B) dyn[(size_t)m * 6 + 2 + o] = a;
    }
}

// ---------------------------------------------------------------------------
extern "C" void kernel_launch(void* const* d_in, const int* in_sizes, int n_in,
                              void* d_out, int out_size) {
    const float* ctx      = (const float*)d_in[0];
    const float* obs_traj = (const float*)d_in[1];
    const float* obs_Me   = (const float*)d_in[2];
    const float* Wih0 = (const float*)d_in[3];
    const float* Whh0 = (const float*)d_in[4];
    const float* bih0 = (const float*)d_in[5];
    const float* bhh0 = (const float*)d_in[6];
    const float* Wih1 = (const float*)d_in[7];
    const float* Whh1 = (const float*)d_in[8];
    const float* bih1 = (const float*)d_in[9];
    const float* bhh1 = (const float*)d_in[10];
    const float* Wihs = (const float*)d_in[11];
    const float* Whhs = (const float*)d_in[12];
    const float* bihs = (const float*)d_in[13];
    const float* bhhs = (const float*)d_in[14];
    const float* P1  = (const float*)d_in[15];
    const float* p1b = (const float*)d_in[16];
    const float* P2  = (const float*)d_in[17];
    const float* p2b = (const float*)d_in[18];
    const float* A1  = (const float*)d_in[19];
    const float* a1b = (const float*)d_in[20];
    const float* A2  = (const float*)d_in[21];
    const float* a2b = (const float*)d_in[22];
    const float* Cw  = (const float*)d_in[23];
    const float* cb  = (const float*)d_in[24];
    float* out = (float*)d_out;

    int B = in_sizes[0] / CTXD;
    if (B > BMAX) B = BMAX;
    int T = in_sizes[1] / (2 * B);
    int TS = T - 1;

    float *h0a, *h0b, *h1a, *h1b, *obsin, *dynA, *dynB, *gictx, *wd0, *wdS;
    __half *h0a16, *h0b16, *h1a16, *h1b16, *ctxp16, *wpk;
    cudaGetSymbolAddress((void**)&h0a, g_h0a);
    cudaGetSymbolAddress((void**)&h0b, g_h0b);
    cudaGetSymbolAddress((void**)&h1a, g_h1a);
    cudaGetSymbolAddress((void**)&h1b, g_h1b);
    cudaGetSymbolAddress((void**)&h0a16, g_h0a16);
    cudaGetSymbolAddress((void**)&h0b16, g_h0b16);
    cudaGetSymbolAddress((void**)&h1a16, g_h1a16);
    cudaGetSymbolAddress((void**)&h1b16, g_h1b16);
    cudaGetSymbolAddress((void**)&ctxp16, g_ctxp16);
    cudaGetSymbolAddress((void**)&obsin, g_obsin);
    cudaGetSymbolAddress((void**)&dynA, g_dynA);
    cudaGetSymbolAddress((void**)&dynB, g_dynB);
    cudaGetSymbolAddress((void**)&gictx, g_gictx);
    cudaGetSymbolAddress((void**)&wd0, g_wdyn0);
    cudaGetSymbolAddress((void**)&wdS, g_wdynS);
    cudaGetSymbolAddress((void**)&wpk, g_wpack);

    cudaFuncSetAttribute(gru_mma_kernel, cudaFuncAttributeMaxDynamicSharedMemorySize, GRU_SMEM);
    cudaFuncSetAttribute(proj_mma_kernel, cudaFuncAttributeMaxDynamicSharedMemorySize, PROJ_SMEM);

    pack_kernel<<<768, 256>>>(Whh0, 768, 256, 0, 256, 256, O_WHH0, wpk);
    pack_kernel<<<768, 256>>>(Wih1, 768, 256, 0, 256, 256, O_WIH1, wpk);
    pack_kernel<<<768, 256>>>(Whh1, 768, 256, 0, 256, 256, O_WHH1, wpk);
    pack_kernel<<<768, 256>>>(Whhs, 768, 256, 0, 256, 256, O_WHHS, wpk);
    pack_kernel<<<384, 256>>>(Wihs, 768, 134, 0, 128, 128, O_WCTX, wpk);
    pack_kernel<<<128, 256>>>(P1, 128, 256, 0, 256, 256, O_PA, wpk);
    pack_kernel<<<64, 256>>>(A1, 64, 256, 0, 256, 256, O_PA + 128L * 256, wpk);
    wdyn_pack_kernel<<<24, 256>>>(Wih0, 6, 0, wd0);
    wdyn_pack_kernel<<<24, 256>>>(Wihs, 134, 128, wdS);

    zero_kernel<<<264, 256>>>(h0a, B * HDIM);
    zero_kernel<<<264, 256>>>(h1a, B * HDIM);
    prep_kernel<<<(B + 255) / 256, 256>>>(obs_traj, obs_Me, obsin, dynA, B, T);
    ctx_kernel<<<(B + 63) / 64, 256>>>(ctx, Cw, cb, ctxp16, B);

    dim3 cgrid((B + 127) / 128, 8);

    // hoisted decoder ctx input-gates: gi_ctx = ctxp @ Wihs[:, :128].T
    gru_mma_kernel<<<cgrid, 256, GRU_SMEM>>>(ctxp16, 128, 128,
                                             h1a, nullptr, 0,
                                             wpk, O_WCTX, 128, 0L,
                                             nullptr, nullptr, nullptr, 0,
                                             bihs, bhhs, nullptr, nullptr, gictx, B, 1);

    // encoder
    float *h0i = h0a, *h0o = h0b, *h1i = h1a, *h1o = h1b;
    __half *h0i16 = h0a16, *h0o16 = h0b16, *h1i16 = h1a16, *h1o16 = h1b16;
    for (int t = 0; t < TS; t++) {
        gru_mma_kernel<<<cgrid, 256, GRU_SMEM>>>(nullptr, 0, 0,
                                                 h0i, h0i16, (t > 0) ? 1 : 0,
                                                 wpk, 0L, 0, O_WHH0,
                                                 nullptr, wd0, obsin + (size_t)t * B * 6, 6,
                                                 bih0, bhh0, h0o, h0o16, nullptr, B, 0);
        gru_mma_kernel<<<cgrid, 256, GRU_SMEM>>>(h0o16, 256, 256,
                                                 h1i, h1i16, (t > 0) ? 1 : 0,
                                                 wpk, O_WIH1, 256, O_WHH1,
                                                 nullptr, nullptr, nullptr, 0,
                                                 bih1, bhh1, h1o, h1o16, nullptr, B, 0);
        float* t0 = h0i; h0i = h0o; h0o = t0;
        float* t1 = h1i; h1i = h1o; h1o = t1;
        __half* s0 = h0i16; h0i16 = h0o16; h0o16 = s0;
        __half* s1 = h1i16; h1i16 = h1o16; h1o16 = s1;
    }

    // decoder
    float* dhi = h1i;
    float* dho = h1o;
    __half* dhi16 = h1i16;
    __half* dho16 = h1o16;
    float* dyi = dynA;
    float* dyo = dynB;
    for (int s = 0; s < PRED; s++) {
        gru_mma_kernel<<<cgrid, 256, GRU_SMEM>>>(nullptr, 0, 0,
                                                 dhi, dhi16, 1,
                                                 wpk, 0L, 0, O_WHHS,
                                                 gictx, wdS, dyi, 6,
                                                 bihs, bhhs, dho, dho16, nullptr, B, 0);
        proj_mma_kernel<<<(B + 127) / 128, 256, PROJ_SMEM>>>(dho16, wpk, p1b, a1b,
                                                             P2, p2b, A2, a2b,
                                                             out, dyo, B, s);
        float* td = dhi; dhi = dho; dho = td;
        __half* ts = dhi16; dhi16 = dho16; dho16 = ts;
        float* ty_ = dyi; dyi = dyo; dyo = ty_;
    }
}